// round 13
// baseline (speedup 1.0000x reference)
#include <cuda_runtime.h>
#include <cuda_fp16.h>
#include <cstdint>

#define Hd   128
#define Wd   128
#define CIN  64
#define HWd  (Hd * Wd)
#define Bn   8

// ---------------- scratch (device globals; allocation is forbidden) --------
__device__ __align__(16) __half g_off16[Bn * 2 * CIN * HWd];   // offsets (B,2C,H,W) fp16
__device__ __align__(16) __half g_xt_hi[Bn * HWd * CIN];       // x pixel-major fp16
__device__ __align__(16) __half g_xd_hi[Bn * HWd * CIN];       // xdef pixel-major fp16
__device__ __align__(16) __half g_wa_hi[9 * 128 * CIN];        // W_off  (s,O,I) fp16
__device__ __align__(16) __half g_wb_hi[9 *  64 * CIN];        // W_conv (s,O,I) fp16

// ---------------- helpers ---------------------------------------------------
__device__ __forceinline__ uint32_t smem_u32(const void* p) {
    uint32_t a;
    asm("{ .reg .u64 t; cvta.to.shared.u64 t, %1; cvt.u32.u64 %0, t; }"
        : "=r"(a) : "l"(p));
    return a;
}
__device__ __forceinline__ void ldx4(uint32_t& r0, uint32_t& r1, uint32_t& r2,
                                     uint32_t& r3, uint32_t addr) {
    asm volatile("ldmatrix.sync.aligned.m8n8.x4.shared.b16 {%0,%1,%2,%3}, [%4];"
                 : "=r"(r0), "=r"(r1), "=r"(r2), "=r"(r3) : "r"(addr));
}
__device__ __forceinline__ void mma16816(float* d, const uint32_t* a,
                                         uint32_t b0, uint32_t b1) {
    asm volatile("mma.sync.aligned.m16n8k16.row.col.f32.f16.f16.f32 "
                 "{%0,%1,%2,%3}, {%4,%5,%6,%7}, {%8,%9}, {%0,%1,%2,%3};"
                 : "+f"(d[0]), "+f"(d[1]), "+f"(d[2]), "+f"(d[3])
                 : "r"(a[0]), "r"(a[1]), "r"(a[2]), "r"(a[3]), "r"(b0), "r"(b1));
}
// cp.async 16B with zero-fill when pred==false (src still a valid address)
__device__ __forceinline__ void cpa16(uint32_t dst, const void* src, bool pred) {
    asm volatile("cp.async.cg.shared.global [%0], [%1], 16, %2;"
                 :: "r"(dst), "l"(src), "r"(pred ? 16u : 0u));
}
#define CP_COMMIT()  asm volatile("cp.async.commit_group;" ::: "memory")
#define CP_WAIT0()   asm volatile("cp.async.wait_group 0;" ::: "memory")
#define CP_WAIT1()   asm volatile("cp.async.wait_group 1;" ::: "memory")

// ---------------------------------------------------------------------------
// Transpose to pixel-major fp16: x (B,C,H,W) f32 -> (B,H,W,C) half.
// ---------------------------------------------------------------------------
__global__ void __launch_bounds__(256)
xpose_kernel(const float* __restrict__ x, __half* __restrict__ hi)
{
    __shared__ float s[CIN][Wd + 1];
    const int tid = threadIdx.x;
    const int y = blockIdx.x & (Hd - 1);
    const int b = blockIdx.x >> 7;

    for (int idx = tid; idx < CIN * Wd; idx += 256) {
        const int c = idx >> 7, xx = idx & (Wd - 1);
        s[c][xx] = x[(((size_t)b * CIN + c) * Hd + y) * Wd + xx];
    }
    __syncthreads();
    for (int idx = tid; idx < Wd * (CIN / 2); idx += 256) {
        const int xx = idx >> 5, cp = idx & 31;
        const __half h0 = __float2half_rn(s[2 * cp][xx]);
        const __half h1 = __float2half_rn(s[2 * cp + 1][xx]);
        const size_t base = ((size_t)(b * Hd + y) * Wd + xx) * CIN + 2 * cp;
        *reinterpret_cast<__half2*>(hi + base) = __halves2half2(h0, h1);
    }
}

// ---------------------------------------------------------------------------
// Weight transform: W (O, CIN, 3, 3) f32 -> (s, O, CIN) fp16.
// ---------------------------------------------------------------------------
__global__ void __launch_bounds__(256)
wsplit_kernel(const float* __restrict__ w, __half* __restrict__ hi, int O)
{
    const int idx = blockIdx.x * 256 + threadIdx.x;
    if (idx >= 9 * O * CIN) return;
    const int i = idx & (CIN - 1);
    const int o = (idx >> 6) % O;
    const int s = idx / (CIN * O);
    hi[idx] = __float2half_rn(w[((size_t)o * CIN + i) * 9 + s]);
}

// ---------------------------------------------------------------------------
// Implicit-GEMM 3x3 conv via mma.sync (HMMA fp16, fp32 accum), cp.async.
// NBSLOT=3: B staged for all 3 dx of a dy at once (dy-outer, 6 barriers).
// NBSLOT=2: B per-shift double-buffered (smaller smem -> 3 CTAs/SM).
// OUTT: float or __half output.
// CTA = one (b, y) row: M=128 pixels, N=COUT.
// ---------------------------------------------------------------------------
template <int COUT, int WARPS_M, int WARPS_N, int MINB, int NBSLOT, typename OUTT>
__global__ void __launch_bounds__(256, MINB)
conv_mma_kernel(const __half* __restrict__ a_src,
                const __half* __restrict__ w_src,
                const float* __restrict__ bias, OUTT* __restrict__ out)
{
    constexpr int WM = 128 / WARPS_M;
    constexpr int WN = COUT / WARPS_N;
    constexpr int MF = WM / 16;
    constexpr int NF = WN / 8;
    constexpr int LDA = 72;                  // 144B rows: ldmatrix conflict-free
    constexpr int LDB = 72;
    constexpr int ASEG = 130 * LDA;          // halves per A buffer
    constexpr int BSEG = COUT * LDB;         // halves per B slot
    constexpr int BOFF = 2 * ASEG;           // halves offset of B region

    extern __shared__ __align__(16) __half smem[];
    const uint32_t sb = smem_u32(smem);

    const int tid  = threadIdx.x;
    const int lane = tid & 31, wid = tid >> 5;
    const int wm = wid % WARPS_M, wn = wid / WARPS_M;
    const int m0 = wm * WM, n0 = wn * WN;
    const int y = blockIdx.x & (Hd - 1);
    const int b = blockIdx.x >> 7;

    auto stageA = [&](int buf, int dy) {
        const int yy = y + dy - 1;
        const bool rowok = (unsigned)yy < (unsigned)Hd;
        const uint32_t dh = sb + (uint32_t)(buf * ASEG) * 2;
        for (int idx = tid; idx < 130 * 8; idx += 256) {
            const int p = idx >> 3, j = idx & 7;
            const int xx = p - 1;
            const bool ok = rowok && (unsigned)xx < (unsigned)Wd;
            const size_t base = ok ? (((size_t)((b * Hd + yy) * Wd + xx)) * CIN + j * 8) : 0;
            const uint32_t doff = (uint32_t)(p * LDA + j * 8) * 2;
            cpa16(dh + doff, a_src + base, ok);
        }
    };
    // stage one B shift into slot
    auto stageB1 = [&](int slot, int s) {
        const uint32_t dh = sb + (uint32_t)(BOFF + slot * BSEG) * 2;
        for (int idx = tid; idx < COUT * 8; idx += 256) {
            const int o = idx >> 3, j = idx & 7;
            const size_t base = ((size_t)(s * COUT) + o) * CIN + j * 8;
            const uint32_t doff = (uint32_t)(o * LDB + j * 8) * 2;
            cpa16(dh + doff, w_src + base, true);
        }
    };
    // stage B for all 3 dx shifts of row-group dy: [dx][COUT][LDB]
    auto stageB3 = [&](int dy) {
        const int s0 = dy * 3;
        const uint32_t dh = sb + (uint32_t)BOFF * 2;
        for (int idx = tid; idx < 3 * COUT * 8; idx += 256) {
            const int op = idx >> 3, j = idx & 7;      // op = dx*COUT + o
            const size_t base = ((size_t)(s0 * COUT) + op) * CIN + j * 8;
            const uint32_t doff = (uint32_t)(op * LDB + j * 8) * 2;
            cpa16(dh + doff, w_src + base, true);
        }
    };

    float d[MF][NF][4];
#pragma unroll
    for (int i = 0; i < MF; i++)
#pragma unroll
        for (int j = 0; j < NF; j++)
#pragma unroll
            for (int k = 0; k < 4; k++) d[i][j][k] = 0.0f;

    const int a_row = lane & 15;
    const int a_k   = (lane >> 4) << 3;
    const int b_row = ((lane >> 4) << 3) + (lane & 7);
    const int b_k   = ((lane >> 3) & 1) << 3;

    auto compute = [&](int dx, uint32_t uAh, uint32_t uB) {
#pragma unroll
        for (int kk = 0; kk < 4; kk++) {
            uint32_t ah[MF][4];
#pragma unroll
            for (int mf = 0; mf < MF; mf++) {
                const uint32_t off =
                    (uint32_t)((m0 + mf * 16 + a_row + dx) * LDA + kk * 16 + a_k) * 2;
                ldx4(ah[mf][0], ah[mf][1], ah[mf][2], ah[mf][3], uAh + off);
            }
#pragma unroll
            for (int nfp = 0; nfp < NF / 2; nfp++) {
                const uint32_t boff =
                    (uint32_t)((n0 + nfp * 16 + b_row) * LDB + kk * 16 + b_k) * 2;
                uint32_t h0, h1, h2, h3;
                ldx4(h0, h1, h2, h3, uB + boff);
#pragma unroll
                for (int mf = 0; mf < MF; mf++) {
                    mma16816(d[mf][2 * nfp],     ah[mf], h0, h1);
                    mma16816(d[mf][2 * nfp + 1], ah[mf], h2, h3);
                }
            }
        }
    };

    if (NBSLOT == 3) {
        // ---- dy-outer: B all-3-dx per dy ----
        stageA(0, 0); stageA(1, 1); stageB3(0); CP_COMMIT();
#pragma unroll 1
        for (int dy = 0; dy < 3; dy++) {
            CP_WAIT0();
            __syncthreads();
            const uint32_t uAh = sb + (uint32_t)((dy & 1) * ASEG) * 2;
#pragma unroll 1
            for (int dx = 0; dx < 3; dx++)
                compute(dx, uAh, sb + (uint32_t)(BOFF + dx * BSEG) * 2);
            __syncthreads();
            if (dy < 2) {
                if (dy == 0) stageA(0, 2);
                stageB3(dy + 1);
            }
            CP_COMMIT();
        }
    } else {
        // ---- per-shift B double buffer (small smem -> 3 CTAs/SM) ----
        stageA(0, 0); stageA(1, 1); stageB1(0, 0); CP_COMMIT();
        stageB1(1, 1); CP_COMMIT();
#pragma unroll 1
        for (int s = 0; s < 9; s++) {
            CP_WAIT1();
            __syncthreads();
            const int dy = s / 3, dx = s % 3;
            compute(dx, sb + (uint32_t)((dy & 1) * ASEG) * 2,
                        sb + (uint32_t)(BOFF + (s & 1) * BSEG) * 2);
            __syncthreads();
            if (s <= 6) stageB1(s & 1, s + 2);
            if (s == 2) stageA(0, 2);
            CP_COMMIT();
        }
    }

    // ---- single-pass epilogue through smem, coalesced STG ----
    float* sEp = reinterpret_cast<float*>(smem);   // COUT x 132
#pragma unroll
    for (int mf = 0; mf < MF; mf++) {
#pragma unroll
        for (int nf = 0; nf < NF; nf++) {
            const int xl = m0 + mf * 16 + (lane >> 2);
            const int c  = n0 + nf * 8 + (lane & 3) * 2;
            sEp[ c      * 132 + xl    ] = d[mf][nf][0];
            sEp[(c + 1) * 132 + xl    ] = d[mf][nf][1];
            sEp[ c      * 132 + xl + 8] = d[mf][nf][2];
            sEp[(c + 1) * 132 + xl + 8] = d[mf][nf][3];
        }
    }
    __syncthreads();
    if (sizeof(OUTT) == 2) {
        // half2 stores, 2 pixels per thread
        for (int idx = tid; idx < COUT * 64; idx += 256) {
            const int c = idx >> 6, qp = idx & 63;
            float v0 = sEp[c * 132 + 2 * qp];
            float v1 = sEp[c * 132 + 2 * qp + 1];
            if (bias) { const float bv = __ldg(bias + c); v0 += bv; v1 += bv; }
            __half2* o2 = reinterpret_cast<__half2*>(
                (__half*)out + (((size_t)b * COUT + c) * Hd + y) * Wd + 2 * qp);
            *o2 = __floats2half2_rn(v0, v1);
        }
    } else {
        for (int idx = tid; idx < COUT * 128; idx += 256) {
            const int c = idx >> 7, q = idx & 127;
            float v = sEp[c * 132 + q];
            if (bias) v += __ldg(bias + c);
            ((float*)out)[(((size_t)b * COUT + c) * Hd + y) * Wd + q] = v;
        }
    }
}

// ---------------------------------------------------------------------------
// Plane-local deformable gather -> pixel-major fp16. Offsets read as fp16.
// Block = 256 consecutive pixels; loop over channels (sector locality).
// ---------------------------------------------------------------------------
__global__ void __launch_bounds__(256)
gather_kernel(const float* __restrict__ x,        // (B, C, H, W)
              const __half* __restrict__ off,     // (B, 2C, H, W) fp16
              __half* __restrict__ xd_hi)
{
    constexpr int LDC = 68;
    extern __shared__ __align__(16) __half gsm[]; // s_hi[256][68]
    __half* s_hi = gsm;

    const int t  = threadIdx.x;
    const int p0 = blockIdx.x * 256;
    const int b  = blockIdx.y;
    const int p  = p0 + t;

    const float gy = (float)(p >> 7);
    const float gx = (float)(p & 127);
    const int   t2 = 2 * p;
    const int   chb = t2 >> 14;
    const int   pos = t2 & (HWd - 1);
    const __half* offb = off + (size_t)b * (2 * CIN) * HWd + pos;
    const float* xb   = x + (size_t)b * CIN * HWd;

#pragma unroll 1
    for (int c = 0; c < CIN; c++) {
        const __half2 oh = *reinterpret_cast<const __half2*>(
            offb + (size_t)(2 * c + chb) * HWd);
        const float2 o2 = __half22float2(oh);

        float cy = o2.x + gy;
        float cx = o2.y + gx;
        cy = fminf(fmaxf(cy, 0.0f), (float)(Hd - 1));
        cx = fminf(fmaxf(cx, 0.0f), (float)(Wd - 1));

        const float y0f = floorf(cy), y1f = ceilf(cy);
        const float x0f = floorf(cx), x1f = ceilf(cx);
        const int y0 = (int)y0f, y1 = (int)y1f;
        const int x0 = (int)x0f, x1 = (int)x1f;

        const float* xp = xb + (size_t)c * HWd;
        const float v_lt = xp[y0 * Wd + x0];
        const float v_rb = xp[y1 * Wd + x1];
        const float v_lb = xp[y0 * Wd + x1];
        const float v_rt = xp[y1 * Wd + x0];

        const float dyf = cy - y0f;
        const float dxf = cx - x0f;
        const float v_t = dyf * (v_rt - v_lt) + v_lt;
        const float v_b = dyf * (v_rb - v_lb) + v_lb;
        const float res = dxf * (v_b - v_t) + v_t;

        s_hi[t * LDC + c] = __float2half_rn(res);
    }
    __syncthreads();

    // coalesced pixel-major writes: per pixel 64 ch = 128B
    for (int idx = t; idx < 256 * 16; idx += 256) {
        const int pp = idx >> 4, j = idx & 15;
        const uint2 vh = *reinterpret_cast<const uint2*>(s_hi + pp * LDC + j * 4);
        const size_t o = ((size_t)b * HWd + p0 + pp) * CIN + j * 4;
        *reinterpret_cast<uint2*>(xd_hi + o) = vh;
    }
}

// ---------------------------------------------------------------------------
extern "C" void kernel_launch(void* const* d_in, const int* in_sizes, int n_in,
                              void* d_out, int out_size)
{
    const float* x      = (const float*)d_in[0];
    const float* W_off  = (const float*)d_in[1];
    const float* W_conv = (const float*)d_in[2];
    const float* b_conv = (const float*)d_in[3];
    float* out = (float*)d_out;

    __half *off_p, *xt_hi, *xd_hi, *wa_hi, *wb_hi;
    cudaGetSymbolAddress((void**)&off_p, g_off16);
    cudaGetSymbolAddress((void**)&xt_hi, g_xt_hi);
    cudaGetSymbolAddress((void**)&xd_hi, g_xd_hi);
    cudaGetSymbolAddress((void**)&wa_hi, g_wa_hi);
    cudaGetSymbolAddress((void**)&wb_hi, g_wb_hi);

    // smem (halves -> bytes)
    const int SMEM_A = (2 * 130 * 72 + 2 * 128 * 72) * 2;   // 74304: 3 CTAs/SM
    const int SMEM_B = (2 * 130 * 72 + 3 *  64 * 72) * 2;   // 65088: 3 CTAs/SM
    const int SMEM_G = 256 * 68 * 2;                        // 34816
    cudaFuncSetAttribute((conv_mma_kernel<128, 2, 4, 3, 2, __half>),
                         cudaFuncAttributeMaxDynamicSharedMemorySize, SMEM_A);
    cudaFuncSetAttribute((conv_mma_kernel<64, 4, 2, 3, 3, float>),
                         cudaFuncAttributeMaxDynamicSharedMemorySize, SMEM_B);
    cudaFuncSetAttribute(gather_kernel,
                         cudaFuncAttributeMaxDynamicSharedMemorySize, SMEM_G);

    // 0) layout transforms
    xpose_kernel<<<Bn * Hd, 256>>>(x, xt_hi);
    wsplit_kernel<<<(9 * 128 * CIN + 255) / 256, 256>>>(W_off,  wa_hi, 128);
    wsplit_kernel<<<(9 *  64 * CIN + 255) / 256, 256>>>(W_conv, wb_hi, 64);

    // 1) offset conv (64 -> 128), fp16, per-shift B buffers, fp16 output
    conv_mma_kernel<128, 2, 4, 3, 2, __half><<<Bn * Hd, 256, SMEM_A>>>(
        xt_hi, wa_hi, nullptr, off_p);

    // 2) plane-local deformable gather (fp16 offsets) -> fp16 pixel-major
    gather_kernel<<<dim3(HWd / 256, Bn), 256, SMEM_G>>>(x, off_p, xd_hi);

    // 3) main conv (64 -> 64) + bias, fp16, fp32 output
    conv_mma_kernel<64, 4, 2, 3, 3, float><<<Bn * Hd, 256, SMEM_B>>>(
        xd_hi, wb_hi, b_conv, out);
}

// round 14
// speedup vs baseline: 1.3095x; 1.3095x over previous
#include <cuda_runtime.h>
#include <cuda_fp16.h>
#include <cstdint>

#define Hd   128
#define Wd   128
#define CIN  64
#define HWd  (Hd * Wd)
#define Bn   8

// ---------------- scratch (device globals; allocation is forbidden) --------
__device__ __align__(16) __half g_off16[Bn * 2 * CIN * HWd];   // offsets (B,2C,H,W) fp16
__device__ __align__(16) __half g_xt_hi[Bn * HWd * CIN];       // x pixel-major fp16
__device__ __align__(16) __half g_xd_hi[Bn * HWd * CIN];       // xdef pixel-major fp16
__device__ __align__(16) __half g_wa_hi[9 * 128 * CIN];        // W_off  (s,O,I) fp16
__device__ __align__(16) __half g_wb_hi[9 *  64 * CIN];        // W_conv (s,O,I) fp16

// ---------------- helpers ---------------------------------------------------
__device__ __forceinline__ uint32_t smem_u32(const void* p) {
    uint32_t a;
    asm("{ .reg .u64 t; cvta.to.shared.u64 t, %1; cvt.u32.u64 %0, t; }"
        : "=r"(a) : "l"(p));
    return a;
}
__device__ __forceinline__ void ldx4(uint32_t& r0, uint32_t& r1, uint32_t& r2,
                                     uint32_t& r3, uint32_t addr) {
    asm volatile("ldmatrix.sync.aligned.m8n8.x4.shared.b16 {%0,%1,%2,%3}, [%4];"
                 : "=r"(r0), "=r"(r1), "=r"(r2), "=r"(r3) : "r"(addr));
}
__device__ __forceinline__ void mma16816(float* d, const uint32_t* a,
                                         uint32_t b0, uint32_t b1) {
    asm volatile("mma.sync.aligned.m16n8k16.row.col.f32.f16.f16.f32 "
                 "{%0,%1,%2,%3}, {%4,%5,%6,%7}, {%8,%9}, {%0,%1,%2,%3};"
                 : "+f"(d[0]), "+f"(d[1]), "+f"(d[2]), "+f"(d[3])
                 : "r"(a[0]), "r"(a[1]), "r"(a[2]), "r"(a[3]), "r"(b0), "r"(b1));
}
// cp.async 16B with zero-fill when pred==false (src still a valid address)
__device__ __forceinline__ void cpa16(uint32_t dst, const void* src, bool pred) {
    asm volatile("cp.async.cg.shared.global [%0], [%1], 16, %2;"
                 :: "r"(dst), "l"(src), "r"(pred ? 16u : 0u));
}
#define CP_COMMIT()  asm volatile("cp.async.commit_group;" ::: "memory")
#define CP_WAIT0()   asm volatile("cp.async.wait_group 0;" ::: "memory")

// ---------------------------------------------------------------------------
// Transpose to pixel-major fp16: x (B,C,H,W) f32 -> (B,H,W,C) half.
// ---------------------------------------------------------------------------
__global__ void __launch_bounds__(256)
xpose_kernel(const float* __restrict__ x, __half* __restrict__ hi)
{
    __shared__ float s[CIN][Wd + 1];
    const int tid = threadIdx.x;
    const int y = blockIdx.x & (Hd - 1);
    const int b = blockIdx.x >> 7;

    for (int idx = tid; idx < CIN * Wd; idx += 256) {
        const int c = idx >> 7, xx = idx & (Wd - 1);
        s[c][xx] = x[(((size_t)b * CIN + c) * Hd + y) * Wd + xx];
    }
    __syncthreads();
    for (int idx = tid; idx < Wd * (CIN / 2); idx += 256) {
        const int xx = idx >> 5, cp = idx & 31;
        const __half h0 = __float2half_rn(s[2 * cp][xx]);
        const __half h1 = __float2half_rn(s[2 * cp + 1][xx]);
        const size_t base = ((size_t)(b * Hd + y) * Wd + xx) * CIN + 2 * cp;
        *reinterpret_cast<__half2*>(hi + base) = __halves2half2(h0, h1);
    }
}

// ---------------------------------------------------------------------------
// Weight transform: W (O, CIN, 3, 3) f32 -> (s, O, CIN) fp16.
// ---------------------------------------------------------------------------
__global__ void __launch_bounds__(256)
wsplit_kernel(const float* __restrict__ w, __half* __restrict__ hi, int O)
{
    const int idx = blockIdx.x * 256 + threadIdx.x;
    if (idx >= 9 * O * CIN) return;
    const int i = idx & (CIN - 1);
    const int o = (idx >> 6) % O;
    const int s = idx / (CIN * O);
    hi[idx] = __float2half_rn(w[((size_t)o * CIN + i) * 9 + s]);
}

// ---------------------------------------------------------------------------
// Implicit-GEMM 3x3 conv via mma.sync (HMMA fp16, fp32 accum), dy-outer:
// A per-dy double-buffered (cp.async), B staged for all 3 dx of a dy.
// OUTT: float or __half output. CTA = one (b, y) row: M=128, N=COUT.
// ---------------------------------------------------------------------------
template <int COUT, int WARPS_M, int WARPS_N, int MINB, typename OUTT>
__global__ void __launch_bounds__(256, MINB)
conv_mma_kernel(const __half* __restrict__ a_src,
                const __half* __restrict__ w_src,
                const float* __restrict__ bias, OUTT* __restrict__ out)
{
    constexpr int WM = 128 / WARPS_M;
    constexpr int WN = COUT / WARPS_N;
    constexpr int MF = WM / 16;
    constexpr int NF = WN / 8;
    constexpr int LDA = 72;                  // 144B rows: ldmatrix conflict-free
    constexpr int LDB = 72;
    constexpr int ASEG = 130 * LDA;          // halves per A buffer
    constexpr int BSEG = COUT * LDB;         // halves per B shift slot
    constexpr int BOFF = 2 * ASEG;           // halves offset of B region (3 slots)

    extern __shared__ __align__(16) __half smem[];
    const uint32_t sb = smem_u32(smem);

    const int tid  = threadIdx.x;
    const int lane = tid & 31, wid = tid >> 5;
    const int wm = wid % WARPS_M, wn = wid / WARPS_M;
    const int m0 = wm * WM, n0 = wn * WN;
    const int y = blockIdx.x & (Hd - 1);
    const int b = blockIdx.x >> 7;

    auto stageA = [&](int buf, int dy) {
        const int yy = y + dy - 1;
        const bool rowok = (unsigned)yy < (unsigned)Hd;
        const uint32_t dh = sb + (uint32_t)(buf * ASEG) * 2;
        for (int idx = tid; idx < 130 * 8; idx += 256) {
            const int p = idx >> 3, j = idx & 7;
            const int xx = p - 1;
            const bool ok = rowok && (unsigned)xx < (unsigned)Wd;
            const size_t base = ok ? (((size_t)((b * Hd + yy) * Wd + xx)) * CIN + j * 8) : 0;
            const uint32_t doff = (uint32_t)(p * LDA + j * 8) * 2;
            cpa16(dh + doff, a_src + base, ok);
        }
    };
    // stage B for all 3 dx shifts of row-group dy: [dx][COUT][LDB]
    auto stageB3 = [&](int dy) {
        const int s0 = dy * 3;
        const uint32_t dh = sb + (uint32_t)BOFF * 2;
        for (int idx = tid; idx < 3 * COUT * 8; idx += 256) {
            const int op = idx >> 3, j = idx & 7;      // op = dx*COUT + o
            const size_t base = ((size_t)(s0 * COUT) + op) * CIN + j * 8;
            const uint32_t doff = (uint32_t)(op * LDB + j * 8) * 2;
            cpa16(dh + doff, w_src + base, true);
        }
    };

    float d[MF][NF][4];
#pragma unroll
    for (int i = 0; i < MF; i++)
#pragma unroll
        for (int j = 0; j < NF; j++)
#pragma unroll
            for (int k = 0; k < 4; k++) d[i][j][k] = 0.0f;

    const int a_row = lane & 15;
    const int a_k   = (lane >> 4) << 3;
    const int b_row = ((lane >> 4) << 3) + (lane & 7);
    const int b_k   = ((lane >> 3) & 1) << 3;

    // ---- prologue: A(dy0), A(dy1), B(dy0) in one group ----
    stageA(0, 0); stageA(1, 1); stageB3(0); CP_COMMIT();

#pragma unroll 1
    for (int dy = 0; dy < 3; dy++) {
        CP_WAIT0();
        __syncthreads();

        const uint32_t uAh = sb + (uint32_t)((dy & 1) * ASEG) * 2;

#pragma unroll 1
        for (int dx = 0; dx < 3; dx++) {
            const uint32_t uB = sb + (uint32_t)(BOFF + dx * BSEG) * 2;
#pragma unroll
            for (int kk = 0; kk < 4; kk++) {
                uint32_t ah[MF][4];
#pragma unroll
                for (int mf = 0; mf < MF; mf++) {
                    const uint32_t off =
                        (uint32_t)((m0 + mf * 16 + a_row + dx) * LDA + kk * 16 + a_k) * 2;
                    ldx4(ah[mf][0], ah[mf][1], ah[mf][2], ah[mf][3], uAh + off);
                }
#pragma unroll
                for (int nfp = 0; nfp < NF / 2; nfp++) {
                    const uint32_t boff =
                        (uint32_t)((n0 + nfp * 16 + b_row) * LDB + kk * 16 + b_k) * 2;
                    uint32_t h0, h1, h2, h3;
                    ldx4(h0, h1, h2, h3, uB + boff);
#pragma unroll
                    for (int mf = 0; mf < MF; mf++) {
                        mma16816(d[mf][2 * nfp],     ah[mf], h0, h1);
                        mma16816(d[mf][2 * nfp + 1], ah[mf], h2, h3);
                    }
                }
            }
        }
        __syncthreads();   // B slots + A buffer free to restage

        if (dy < 2) {
            if (dy == 0) stageA(0, 2);   // A(dy2) into buf 0
            stageB3(dy + 1);
        }
        CP_COMMIT();
    }

    // ---- single-pass epilogue through smem, coalesced STG ----
    float* sEp = reinterpret_cast<float*>(smem);   // COUT x 132
#pragma unroll
    for (int mf = 0; mf < MF; mf++) {
#pragma unroll
        for (int nf = 0; nf < NF; nf++) {
            const int xl = m0 + mf * 16 + (lane >> 2);
            const int c  = n0 + nf * 8 + (lane & 3) * 2;
            sEp[ c      * 132 + xl    ] = d[mf][nf][0];
            sEp[(c + 1) * 132 + xl    ] = d[mf][nf][1];
            sEp[ c      * 132 + xl + 8] = d[mf][nf][2];
            sEp[(c + 1) * 132 + xl + 8] = d[mf][nf][3];
        }
    }
    __syncthreads();
    if (sizeof(OUTT) == 2) {
        // half2 stores, 2 pixels per thread
        for (int idx = tid; idx < COUT * 64; idx += 256) {
            const int c = idx >> 6, qp = idx & 63;
            float v0 = sEp[c * 132 + 2 * qp];
            float v1 = sEp[c * 132 + 2 * qp + 1];
            if (bias) { const float bv = __ldg(bias + c); v0 += bv; v1 += bv; }
            __half2* o2 = reinterpret_cast<__half2*>(
                (__half*)out + (((size_t)b * COUT + c) * Hd + y) * Wd + 2 * qp);
            *o2 = __floats2half2_rn(v0, v1);
        }
    } else {
        for (int idx = tid; idx < COUT * 128; idx += 256) {
            const int c = idx >> 7, q = idx & 127;
            float v = sEp[c * 132 + q];
            if (bias) v += __ldg(bias + c);
            ((float*)out)[(((size_t)b * COUT + c) * Hd + y) * Wd + q] = v;
        }
    }
}

// ---------------------------------------------------------------------------
// Plane-local deformable gather -> pixel-major fp16. Offsets read as fp16.
// Block = 256 consecutive pixels; loop over channels (sector locality).
// ---------------------------------------------------------------------------
__global__ void __launch_bounds__(256)
gather_kernel(const float* __restrict__ x,        // (B, C, H, W)
              const __half* __restrict__ off,     // (B, 2C, H, W) fp16
              __half* __restrict__ xd_hi)
{
    constexpr int LDC = 68;
    extern __shared__ __align__(16) __half gsm[]; // s_hi[256][68]
    __half* s_hi = gsm;

    const int t  = threadIdx.x;
    const int p0 = blockIdx.x * 256;
    const int b  = blockIdx.y;
    const int p  = p0 + t;

    const float gy = (float)(p >> 7);
    const float gx = (float)(p & 127);
    const int   t2 = 2 * p;
    const int   chb = t2 >> 14;
    const int   pos = t2 & (HWd - 1);
    const __half* offb = off + (size_t)b * (2 * CIN) * HWd + pos;
    const float* xb   = x + (size_t)b * CIN * HWd;

#pragma unroll 1
    for (int c = 0; c < CIN; c++) {
        const __half2 oh = *reinterpret_cast<const __half2*>(
            offb + (size_t)(2 * c + chb) * HWd);
        const float2 o2 = __half22float2(oh);

        float cy = o2.x + gy;
        float cx = o2.y + gx;
        cy = fminf(fmaxf(cy, 0.0f), (float)(Hd - 1));
        cx = fminf(fmaxf(cx, 0.0f), (float)(Wd - 1));

        const float y0f = floorf(cy), y1f = ceilf(cy);
        const float x0f = floorf(cx), x1f = ceilf(cx);
        const int y0 = (int)y0f, y1 = (int)y1f;
        const int x0 = (int)x0f, x1 = (int)x1f;

        const float* xp = xb + (size_t)c * HWd;
        const float v_lt = xp[y0 * Wd + x0];
        const float v_rb = xp[y1 * Wd + x1];
        const float v_lb = xp[y0 * Wd + x1];
        const float v_rt = xp[y1 * Wd + x0];

        const float dyf = cy - y0f;
        const float dxf = cx - x0f;
        const float v_t = dyf * (v_rt - v_lt) + v_lt;
        const float v_b = dyf * (v_rb - v_lb) + v_lb;
        const float res = dxf * (v_b - v_t) + v_t;

        s_hi[t * LDC + c] = __float2half_rn(res);
    }
    __syncthreads();

    // coalesced pixel-major writes: per pixel 64 ch = 128B
    for (int idx = t; idx < 256 * 16; idx += 256) {
        const int pp = idx >> 4, j = idx & 15;
        const uint2 vh = *reinterpret_cast<const uint2*>(s_hi + pp * LDC + j * 4);
        const size_t o = ((size_t)b * HWd + p0 + pp) * CIN + j * 4;
        *reinterpret_cast<uint2*>(xd_hi + o) = vh;
    }
}

// ---------------------------------------------------------------------------
extern "C" void kernel_launch(void* const* d_in, const int* in_sizes, int n_in,
                              void* d_out, int out_size)
{
    const float* x      = (const float*)d_in[0];
    const float* W_off  = (const float*)d_in[1];
    const float* W_conv = (const float*)d_in[2];
    const float* b_conv = (const float*)d_in[3];
    float* out = (float*)d_out;

    __half *off_p, *xt_hi, *xd_hi, *wa_hi, *wb_hi;
    cudaGetSymbolAddress((void**)&off_p, g_off16);
    cudaGetSymbolAddress((void**)&xt_hi, g_xt_hi);
    cudaGetSymbolAddress((void**)&xd_hi, g_xd_hi);
    cudaGetSymbolAddress((void**)&wa_hi, g_wa_hi);
    cudaGetSymbolAddress((void**)&wb_hi, g_wb_hi);

    // smem (halves -> bytes): 2 A bufs + 3 B shift slots
    const int SMEM_A = (2 * 130 * 72 + 3 * 128 * 72) * 2;   // 92736: 2 CTAs/SM, no cap
    const int SMEM_B = (2 * 130 * 72 + 3 *  64 * 72) * 2;   // 65088: 3 CTAs/SM
    const int SMEM_G = 256 * 68 * 2;                        // 34816
    cudaFuncSetAttribute((conv_mma_kernel<128, 2, 4, 2, __half>),
                         cudaFuncAttributeMaxDynamicSharedMemorySize, SMEM_A);
    cudaFuncSetAttribute((conv_mma_kernel<64, 4, 2, 3, float>),
                         cudaFuncAttributeMaxDynamicSharedMemorySize, SMEM_B);
    cudaFuncSetAttribute(gather_kernel,
                         cudaFuncAttributeMaxDynamicSharedMemorySize, SMEM_G);

    // 0) layout transforms
    xpose_kernel<<<Bn * Hd, 256>>>(x, xt_hi);
    wsplit_kernel<<<(9 * 128 * CIN + 255) / 256, 256>>>(W_off,  wa_hi, 128);
    wsplit_kernel<<<(9 *  64 * CIN + 255) / 256, 256>>>(W_conv, wb_hi, 64);

    // 1) offset conv (64 -> 128), fp16, dy-outer, NO reg cap, fp16 output
    conv_mma_kernel<128, 2, 4, 2, __half><<<Bn * Hd, 256, SMEM_A>>>(
        xt_hi, wa_hi, nullptr, off_p);

    // 2) plane-local deformable gather (fp16 offsets) -> fp16 pixel-major
    gather_kernel<<<dim3(HWd / 256, Bn), 256, SMEM_G>>>(x, off_p, xd_hi);

    // 3) main conv (64 -> 64) + bias, fp16, 3 CTAs/SM, fp32 output
    conv_mma_kernel<64, 4, 2, 3, float><<<Bn * Hd, 256, SMEM_B>>>(
        xd_hi, wb_hi, b_conv, out);
}

// round 15
// speedup vs baseline: 1.5559x; 1.1881x over previous
#include <cuda_runtime.h>
#include <cuda_fp16.h>
#include <cstdint>

#define Hd   128
#define Wd   128
#define CIN  64
#define HWd  (Hd * Wd)
#define Bn   8

// ---------------- scratch (device globals; allocation is forbidden) --------
__device__ __align__(16) __half g_off16[Bn * 2 * CIN * HWd];   // offsets (B,2C,H,W) fp16
__device__ __align__(16) __half g_xt_hi[Bn * HWd * CIN];       // x pixel-major fp16
__device__ __align__(16) __half g_xd_hi[Bn * HWd * CIN];       // xdef pixel-major fp16
__device__ __align__(16) __half g_wa_hi[9 * 128 * CIN];        // W_off  (s,O,I) fp16
__device__ __align__(16) __half g_wb_hi[9 *  64 * CIN];        // W_conv (s,O,I) fp16

// ---------------- helpers ---------------------------------------------------
__device__ __forceinline__ uint32_t smem_u32(const void* p) {
    uint32_t a;
    asm("{ .reg .u64 t; cvta.to.shared.u64 t, %1; cvt.u32.u64 %0, t; }"
        : "=r"(a) : "l"(p));
    return a;
}
__device__ __forceinline__ void ldx4(uint32_t& r0, uint32_t& r1, uint32_t& r2,
                                     uint32_t& r3, uint32_t addr) {
    asm volatile("ldmatrix.sync.aligned.m8n8.x4.shared.b16 {%0,%1,%2,%3}, [%4];"
                 : "=r"(r0), "=r"(r1), "=r"(r2), "=r"(r3) : "r"(addr));
}
__device__ __forceinline__ void mma16816(float* d, const uint32_t* a,
                                         uint32_t b0, uint32_t b1) {
    asm volatile("mma.sync.aligned.m16n8k16.row.col.f32.f16.f16.f32 "
                 "{%0,%1,%2,%3}, {%4,%5,%6,%7}, {%8,%9}, {%0,%1,%2,%3};"
                 : "+f"(d[0]), "+f"(d[1]), "+f"(d[2]), "+f"(d[3])
                 : "r"(a[0]), "r"(a[1]), "r"(a[2]), "r"(a[3]), "r"(b0), "r"(b1));
}
// cp.async 16B with zero-fill when pred==false (src still a valid address)
__device__ __forceinline__ void cpa16(uint32_t dst, const void* src, bool pred) {
    asm volatile("cp.async.cg.shared.global [%0], [%1], 16, %2;"
                 :: "r"(dst), "l"(src), "r"(pred ? 16u : 0u));
}
#define CP_COMMIT()  asm volatile("cp.async.commit_group;" ::: "memory")
#define CP_WAIT0()   asm volatile("cp.async.wait_group 0;" ::: "memory")

// ---------------------------------------------------------------------------
// Prep kernel: blocks [0,1024) transpose x -> pixel-major fp16;
// blocks [1024, ...) convert both weight tensors to (s,O,I) fp16.
// ---------------------------------------------------------------------------
#define WA_ELEMS (9 * 128 * CIN)   // 73728
#define WB_ELEMS (9 *  64 * CIN)   // 36864
#define PREP_WBLOCKS ((WA_ELEMS + WB_ELEMS + 255) / 256)   // 432

__global__ void __launch_bounds__(256)
prep_kernel(const float* __restrict__ x, __half* __restrict__ hi,
            const float* __restrict__ wA, __half* __restrict__ waO,
            const float* __restrict__ wB, __half* __restrict__ wbO)
{
    const int tid = threadIdx.x;
    if (blockIdx.x < 1024) {
        __shared__ float s[CIN][Wd + 1];
        const int y = blockIdx.x & (Hd - 1);
        const int b = blockIdx.x >> 7;
        for (int idx = tid; idx < CIN * Wd; idx += 256) {
            const int c = idx >> 7, xx = idx & (Wd - 1);
            s[c][xx] = x[(((size_t)b * CIN + c) * Hd + y) * Wd + xx];
        }
        __syncthreads();
        for (int idx = tid; idx < Wd * (CIN / 2); idx += 256) {
            const int xx = idx >> 5, cp = idx & 31;
            const __half h0 = __float2half_rn(s[2 * cp][xx]);
            const __half h1 = __float2half_rn(s[2 * cp + 1][xx]);
            const size_t base = ((size_t)(b * Hd + y) * Wd + xx) * CIN + 2 * cp;
            *reinterpret_cast<__half2*>(hi + base) = __halves2half2(h0, h1);
        }
    } else {
        const int g = (blockIdx.x - 1024) * 256 + tid;
        if (g < WA_ELEMS) {
            const int i = g & (CIN - 1);
            const int o = (g >> 6) & 127;
            const int s = g / (CIN * 128);
            waO[g] = __float2half_rn(wA[((size_t)o * CIN + i) * 9 + s]);
        } else if (g < WA_ELEMS + WB_ELEMS) {
            const int g2 = g - WA_ELEMS;
            const int i = g2 & (CIN - 1);
            const int o = (g2 >> 6) & 63;
            const int s = g2 / (CIN * 64);
            wbO[g2] = __float2half_rn(wB[((size_t)o * CIN + i) * 9 + s]);
        }
    }
}

// ---------------------------------------------------------------------------
// Implicit-GEMM 3x3 conv via mma.sync (HMMA fp16, fp32 accum), dy-outer:
// A per-dy double-buffered (cp.async), B staged for all 3 dx of a dy.
// CTA = one (b, y) row: M=128, N=COUT.  (conv A: COUT=128, fp16 out)
// ---------------------------------------------------------------------------
template <int COUT, int WARPS_M, int WARPS_N, int MINB, typename OUTT>
__global__ void __launch_bounds__(256, MINB)
conv_mma_kernel(const __half* __restrict__ a_src,
                const __half* __restrict__ w_src,
                const float* __restrict__ bias, OUTT* __restrict__ out)
{
    constexpr int WM = 128 / WARPS_M;
    constexpr int WN = COUT / WARPS_N;
    constexpr int MF = WM / 16;
    constexpr int NF = WN / 8;
    constexpr int LDA = 72;
    constexpr int LDB = 72;
    constexpr int ASEG = 130 * LDA;
    constexpr int BSEG = COUT * LDB;
    constexpr int BOFF = 2 * ASEG;

    extern __shared__ __align__(16) __half smem[];
    const uint32_t sb = smem_u32(smem);

    const int tid  = threadIdx.x;
    const int lane = tid & 31, wid = tid >> 5;
    const int wm = wid % WARPS_M, wn = wid / WARPS_M;
    const int m0 = wm * WM, n0 = wn * WN;
    const int y = blockIdx.x & (Hd - 1);
    const int b = blockIdx.x >> 7;

    auto stageA = [&](int buf, int dy) {
        const int yy = y + dy - 1;
        const bool rowok = (unsigned)yy < (unsigned)Hd;
        const uint32_t dh = sb + (uint32_t)(buf * ASEG) * 2;
        for (int idx = tid; idx < 130 * 8; idx += 256) {
            const int p = idx >> 3, j = idx & 7;
            const int xx = p - 1;
            const bool ok = rowok && (unsigned)xx < (unsigned)Wd;
            const size_t base = ok ? (((size_t)((b * Hd + yy) * Wd + xx)) * CIN + j * 8) : 0;
            const uint32_t doff = (uint32_t)(p * LDA + j * 8) * 2;
            cpa16(dh + doff, a_src + base, ok);
        }
    };
    auto stageB3 = [&](int dy) {
        const int s0 = dy * 3;
        const uint32_t dh = sb + (uint32_t)BOFF * 2;
        for (int idx = tid; idx < 3 * COUT * 8; idx += 256) {
            const int op = idx >> 3, j = idx & 7;
            const size_t base = ((size_t)(s0 * COUT) + op) * CIN + j * 8;
            const uint32_t doff = (uint32_t)(op * LDB + j * 8) * 2;
            cpa16(dh + doff, w_src + base, true);
        }
    };

    float d[MF][NF][4];
#pragma unroll
    for (int i = 0; i < MF; i++)
#pragma unroll
        for (int j = 0; j < NF; j++)
#pragma unroll
            for (int k = 0; k < 4; k++) d[i][j][k] = 0.0f;

    const int a_row = lane & 15;
    const int a_k   = (lane >> 4) << 3;
    const int b_row = ((lane >> 4) << 3) + (lane & 7);
    const int b_k   = ((lane >> 3) & 1) << 3;

    stageA(0, 0); stageA(1, 1); stageB3(0); CP_COMMIT();

#pragma unroll 1
    for (int dy = 0; dy < 3; dy++) {
        CP_WAIT0();
        __syncthreads();
        const uint32_t uAh = sb + (uint32_t)((dy & 1) * ASEG) * 2;

#pragma unroll 1
        for (int dx = 0; dx < 3; dx++) {
            const uint32_t uB = sb + (uint32_t)(BOFF + dx * BSEG) * 2;
#pragma unroll
            for (int kk = 0; kk < 4; kk++) {
                uint32_t ah[MF][4];
#pragma unroll
                for (int mf = 0; mf < MF; mf++) {
                    const uint32_t off =
                        (uint32_t)((m0 + mf * 16 + a_row + dx) * LDA + kk * 16 + a_k) * 2;
                    ldx4(ah[mf][0], ah[mf][1], ah[mf][2], ah[mf][3], uAh + off);
                }
#pragma unroll
                for (int nfp = 0; nfp < NF / 2; nfp++) {
                    const uint32_t boff =
                        (uint32_t)((n0 + nfp * 16 + b_row) * LDB + kk * 16 + b_k) * 2;
                    uint32_t h0, h1, h2, h3;
                    ldx4(h0, h1, h2, h3, uB + boff);
#pragma unroll
                    for (int mf = 0; mf < MF; mf++) {
                        mma16816(d[mf][2 * nfp],     ah[mf], h0, h1);
                        mma16816(d[mf][2 * nfp + 1], ah[mf], h2, h3);
                    }
                }
            }
        }
        __syncthreads();

        if (dy < 2) {
            if (dy == 0) stageA(0, 2);
            stageB3(dy + 1);
        }
        CP_COMMIT();
    }

    // ---- epilogue ----
    float* sEp = reinterpret_cast<float*>(smem);   // COUT x 132
#pragma unroll
    for (int mf = 0; mf < MF; mf++) {
#pragma unroll
        for (int nf = 0; nf < NF; nf++) {
            const int xl = m0 + mf * 16 + (lane >> 2);
            const int c  = n0 + nf * 8 + (lane & 3) * 2;
            sEp[ c      * 132 + xl    ] = d[mf][nf][0];
            sEp[(c + 1) * 132 + xl    ] = d[mf][nf][1];
            sEp[ c      * 132 + xl + 8] = d[mf][nf][2];
            sEp[(c + 1) * 132 + xl + 8] = d[mf][nf][3];
        }
    }
    __syncthreads();
    if (sizeof(OUTT) == 2) {
        for (int idx = tid; idx < COUT * 64; idx += 256) {
            const int c = idx >> 6, qp = idx & 63;
            float v0 = sEp[c * 132 + 2 * qp];
            float v1 = sEp[c * 132 + 2 * qp + 1];
            if (bias) { const float bv = __ldg(bias + c); v0 += bv; v1 += bv; }
            __half2* o2 = reinterpret_cast<__half2*>(
                (__half*)out + (((size_t)b * COUT + c) * Hd + y) * Wd + 2 * qp);
            *o2 = __floats2half2_rn(v0, v1);
        }
    } else {
        for (int idx = tid; idx < COUT * 128; idx += 256) {
            const int c = idx >> 7, q = idx & 127;
            float v = sEp[c * 132 + q];
            if (bias) v += __ldg(bias + c);
            ((float*)out)[(((size_t)b * COUT + c) * Hd + y) * Wd + q] = v;
        }
    }
}

// ---------------------------------------------------------------------------
// conv B: M=256 (two y-rows per CTA), N=64. Warps 4x2 -> MF=4, NF=4 (ratio
// 2.67). A staged as two 130-row halo blocks per dy (no x-wrap contamination).
// grid = 512. fp32 output + bias.
// ---------------------------------------------------------------------------
__global__ void __launch_bounds__(256, 2)
conv_mma2_kernel(const __half* __restrict__ a_src,
                 const __half* __restrict__ w_src,
                 const float* __restrict__ bias, float* __restrict__ out)
{
    constexpr int COUT = 64;
    constexpr int MF = 4, NF = 4;
    constexpr int LDA = 72, LDB = 72;
    constexpr int ASEG = 260 * LDA;          // two 130-row blocks
    constexpr int BSEG = COUT * LDB;
    constexpr int BOFF = 2 * ASEG;

    extern __shared__ __align__(16) __half smem[];
    const uint32_t sb = smem_u32(smem);

    const int tid  = threadIdx.x;
    const int lane = tid & 31, wid = tid >> 5;
    const int wm = wid & 3, wn = wid >> 2;       // 4 x 2 warps
    const int m0 = wm * 64, n0 = wn * 32;
    const int y0 = (blockIdx.x & 63) * 2;
    const int b  = blockIdx.x >> 6;

    auto stageA = [&](int buf, int dy) {
        const uint32_t dh = sb + (uint32_t)(buf * ASEG) * 2;
        for (int idx = tid; idx < 260 * 8; idx += 256) {
            const int r = idx >> 3, j = idx & 7;
            const int blk = (r >= 130);
            const int rr = r - blk * 130;
            const int yy = y0 + dy - 1 + blk;
            const int xx = rr - 1;
            const bool ok = (unsigned)yy < (unsigned)Hd && (unsigned)xx < (unsigned)Wd;
            const size_t base = ok ? (((size_t)((b * Hd + yy) * Wd + xx)) * CIN + j * 8) : 0;
            const uint32_t doff = (uint32_t)(r * LDA + j * 8) * 2;
            cpa16(dh + doff, a_src + base, ok);
        }
    };
    auto stageB3 = [&](int dy) {
        const int s0 = dy * 3;
        const uint32_t dh = sb + (uint32_t)BOFF * 2;
        for (int idx = tid; idx < 3 * COUT * 8; idx += 256) {
            const int op = idx >> 3, j = idx & 7;
            const size_t base = ((size_t)(s0 * COUT) + op) * CIN + j * 8;
            const uint32_t doff = (uint32_t)(op * LDB + j * 8) * 2;
            cpa16(dh + doff, w_src + base, true);
        }
    };

    float d[MF][NF][4];
#pragma unroll
    for (int i = 0; i < MF; i++)
#pragma unroll
        for (int j = 0; j < NF; j++)
#pragma unroll
            for (int k = 0; k < 4; k++) d[i][j][k] = 0.0f;

    const int a_row = lane & 15;
    const int a_k   = (lane >> 4) << 3;
    const int b_row = ((lane >> 4) << 3) + (lane & 7);
    const int b_k   = ((lane >> 3) & 1) << 3;
    const int mbase = m0 + (wm >= 2 ? 2 : 0);    // block1 storage offset (+2 rows)

    stageA(0, 0); stageA(1, 1); stageB3(0); CP_COMMIT();

#pragma unroll 1
    for (int dy = 0; dy < 3; dy++) {
        CP_WAIT0();
        __syncthreads();
        const uint32_t uAh = sb + (uint32_t)((dy & 1) * ASEG) * 2;

#pragma unroll 1
        for (int dx = 0; dx < 3; dx++) {
            const uint32_t uB = sb + (uint32_t)(BOFF + dx * BSEG) * 2;
#pragma unroll
            for (int kk = 0; kk < 4; kk++) {
                uint32_t ah[MF][4];
#pragma unroll
                for (int mf = 0; mf < MF; mf++) {
                    const uint32_t off =
                        (uint32_t)((mbase + mf * 16 + a_row + dx) * LDA + kk * 16 + a_k) * 2;
                    ldx4(ah[mf][0], ah[mf][1], ah[mf][2], ah[mf][3], uAh + off);
                }
#pragma unroll
                for (int nfp = 0; nfp < NF / 2; nfp++) {
                    const uint32_t boff =
                        (uint32_t)((n0 + nfp * 16 + b_row) * LDB + kk * 16 + b_k) * 2;
                    uint32_t h0, h1, h2, h3;
                    ldx4(h0, h1, h2, h3, uB + boff);
#pragma unroll
                    for (int mf = 0; mf < MF; mf++) {
                        mma16816(d[mf][2 * nfp],     ah[mf], h0, h1);
                        mma16816(d[mf][2 * nfp + 1], ah[mf], h2, h3);
                    }
                }
            }
        }
        __syncthreads();

        if (dy < 2) {
            if (dy == 0) stageA(0, 2);
            stageB3(dy + 1);
        }
        CP_COMMIT();
    }

    // ---- epilogue: COUT x 260 fp32 through smem ----
    float* sEp = reinterpret_cast<float*>(smem);
#pragma unroll
    for (int mf = 0; mf < MF; mf++) {
#pragma unroll
        for (int nf = 0; nf < NF; nf++) {
            const int xl = m0 + mf * 16 + (lane >> 2);
            const int c  = n0 + nf * 8 + (lane & 3) * 2;
            sEp[ c      * 260 + xl    ] = d[mf][nf][0];
            sEp[(c + 1) * 260 + xl    ] = d[mf][nf][1];
            sEp[ c      * 260 + xl + 8] = d[mf][nf][2];
            sEp[(c + 1) * 260 + xl + 8] = d[mf][nf][3];
        }
    }
    __syncthreads();
    for (int idx = tid; idx < COUT * 256; idx += 256) {
        const int c = idx >> 8, q = idx & 255;
        float v = sEp[c * 260 + q] + __ldg(bias + c);
        out[(((size_t)b * COUT + c) * Hd + y0 + (q >> 7)) * Wd + (q & 127)] = v;
    }
}

// ---------------------------------------------------------------------------
// Plane-local deformable gather -> pixel-major fp16, 2-channel ILP.
// ---------------------------------------------------------------------------
__global__ void __launch_bounds__(256)
gather_kernel(const float* __restrict__ x,        // (B, C, H, W)
              const __half* __restrict__ off,     // (B, 2C, H, W) fp16
              __half* __restrict__ xd_hi)
{
    constexpr int LDC = 68;
    extern __shared__ __align__(16) __half gsm[]; // s_hi[256][68]
    __half* s_hi = gsm;

    const int t  = threadIdx.x;
    const int p0 = blockIdx.x * 256;
    const int b  = blockIdx.y;
    const int p  = p0 + t;

    const float gy = (float)(p >> 7);
    const float gx = (float)(p & 127);
    const int   t2 = 2 * p;
    const int   chb = t2 >> 14;
    const int   pos = t2 & (HWd - 1);
    const __half* offb = off + (size_t)b * (2 * CIN) * HWd + pos;
    const float* xb   = x + (size_t)b * CIN * HWd;

#pragma unroll 1
    for (int c = 0; c < CIN; c += 2) {
        // two independent channel chains for ILP
        const __half2 oh0 = *reinterpret_cast<const __half2*>(
            offb + (size_t)(2 * c + chb) * HWd);
        const __half2 oh1 = *reinterpret_cast<const __half2*>(
            offb + (size_t)(2 * c + 2 + chb) * HWd);
        const float2 o0 = __half22float2(oh0);
        const float2 o1 = __half22float2(oh1);

        float cy0 = fminf(fmaxf(o0.x + gy, 0.0f), (float)(Hd - 1));
        float cx0 = fminf(fmaxf(o0.y + gx, 0.0f), (float)(Wd - 1));
        float cy1 = fminf(fmaxf(o1.x + gy, 0.0f), (float)(Hd - 1));
        float cx1 = fminf(fmaxf(o1.y + gx, 0.0f), (float)(Wd - 1));

        const float y0f0 = floorf(cy0), y1f0 = ceilf(cy0);
        const float x0f0 = floorf(cx0), x1f0 = ceilf(cx0);
        const float y0f1 = floorf(cy1), y1f1 = ceilf(cy1);
        const float x0f1 = floorf(cx1), x1f1 = ceilf(cx1);

        const float* xp0 = xb + (size_t)c * HWd;
        const float* xp1 = xp0 + HWd;
        const int ia0 = (int)y0f0 * Wd + (int)x0f0;
        const int ib0 = (int)y1f0 * Wd + (int)x1f0;
        const int ic0 = (int)y0f0 * Wd + (int)x1f0;
        const int id0 = (int)y1f0 * Wd + (int)x0f0;
        const int ia1 = (int)y0f1 * Wd + (int)x0f1;
        const int ib1 = (int)y1f1 * Wd + (int)x1f1;
        const int ic1 = (int)y0f1 * Wd + (int)x1f1;
        const int id1 = (int)y1f1 * Wd + (int)x0f1;

        const float v_lt0 = __ldg(xp0 + ia0), v_rb0 = __ldg(xp0 + ib0);
        const float v_lb0 = __ldg(xp0 + ic0), v_rt0 = __ldg(xp0 + id0);
        const float v_lt1 = __ldg(xp1 + ia1), v_rb1 = __ldg(xp1 + ib1);
        const float v_lb1 = __ldg(xp1 + ic1), v_rt1 = __ldg(xp1 + id1);

        const float dy0 = cy0 - y0f0, dx0 = cx0 - x0f0;
        const float dy1 = cy1 - y0f1, dx1 = cx1 - x0f1;
        const float vt0 = dy0 * (v_rt0 - v_lt0) + v_lt0;
        const float vb0 = dy0 * (v_rb0 - v_lb0) + v_lb0;
        const float vt1 = dy1 * (v_rt1 - v_lt1) + v_lt1;
        const float vb1 = dy1 * (v_rb1 - v_lb1) + v_lb1;

        s_hi[t * LDC + c]     = __float2half_rn(dx0 * (vb0 - vt0) + vt0);
        s_hi[t * LDC + c + 1] = __float2half_rn(dx1 * (vb1 - vt1) + vt1);
    }
    __syncthreads();

    for (int idx = t; idx < 256 * 16; idx += 256) {
        const int pp = idx >> 4, j = idx & 15;
        const uint2 vh = *reinterpret_cast<const uint2*>(s_hi + pp * LDC + j * 4);
        const size_t o = ((size_t)b * HWd + p0 + pp) * CIN + j * 4;
        *reinterpret_cast<uint2*>(xd_hi + o) = vh;
    }
}

// ---------------------------------------------------------------------------
extern "C" void kernel_launch(void* const* d_in, const int* in_sizes, int n_in,
                              void* d_out, int out_size)
{
    const float* x      = (const float*)d_in[0];
    const float* W_off  = (const float*)d_in[1];
    const float* W_conv = (const float*)d_in[2];
    const float* b_conv = (const float*)d_in[3];
    float* out = (float*)d_out;

    __half *off_p, *xt_hi, *xd_hi, *wa_hi, *wb_hi;
    cudaGetSymbolAddress((void**)&off_p, g_off16);
    cudaGetSymbolAddress((void**)&xt_hi, g_xt_hi);
    cudaGetSymbolAddress((void**)&xd_hi, g_xd_hi);
    cudaGetSymbolAddress((void**)&wa_hi, g_wa_hi);
    cudaGetSymbolAddress((void**)&wb_hi, g_wb_hi);

    const int SMEM_A  = (2 * 130 * 72 + 3 * 128 * 72) * 2;   // 92736
    const int SMEM_B2 = (2 * 260 * 72 + 3 *  64 * 72) * 2;   // 102528
    const int SMEM_G  = 256 * 68 * 2;                        // 34816
    cudaFuncSetAttribute((conv_mma_kernel<128, 2, 4, 2, __half>),
                         cudaFuncAttributeMaxDynamicSharedMemorySize, SMEM_A);
    cudaFuncSetAttribute(conv_mma2_kernel,
                         cudaFuncAttributeMaxDynamicSharedMemorySize, SMEM_B2);
    cudaFuncSetAttribute(gather_kernel,
                         cudaFuncAttributeMaxDynamicSharedMemorySize, SMEM_G);

    // 0) prep: transpose + both weight converts in one launch
    prep_kernel<<<1024 + PREP_WBLOCKS, 256>>>(x, xt_hi, W_off, wa_hi, W_conv, wb_hi);

    // 1) offset conv (64 -> 128), fp16, dy-outer, fp16 output
    conv_mma_kernel<128, 2, 4, 2, __half><<<Bn * Hd, 256, SMEM_A>>>(
        xt_hi, wa_hi, nullptr, off_p);

    // 2) plane-local deformable gather (fp16 offsets) -> fp16 pixel-major
    gather_kernel<<<dim3(HWd / 256, Bn), 256, SMEM_G>>>(x, off_p, xd_hi);

    // 3) main conv (64 -> 64) + bias, M=256 tiles, fp32 output
    conv_mma2_kernel<<<512, 256, SMEM_B2>>>(xd_hi, wb_hi, b_conv, out);
}

// round 16
// speedup vs baseline: 1.6257x; 1.0449x over previous
#include <cuda_runtime.h>
#include <cuda_fp16.h>
#include <cstdint>

#define Hd   128
#define Wd   128
#define CIN  64
#define HWd  (Hd * Wd)
#define Bn   8

// ---------------- scratch (device globals; allocation is forbidden) --------
__device__ __align__(16) __half g_off16[Bn * 2 * CIN * HWd];   // offsets (B,2C,H,W) fp16
__device__ __align__(16) __half g_xt_hi[Bn * HWd * CIN];       // x pixel-major fp16
__device__ __align__(16) __half g_xd_hi[Bn * HWd * CIN];       // xdef pixel-major fp16
__device__ __align__(16) __half g_wa_hi[9 * 128 * CIN];        // W_off  (s,O,I) fp16
__device__ __align__(16) __half g_wb_hi[9 *  64 * CIN];        // W_conv (s,O,I) fp16

// ---------------- helpers ---------------------------------------------------
__device__ __forceinline__ uint32_t smem_u32(const void* p) {
    uint32_t a;
    asm("{ .reg .u64 t; cvta.to.shared.u64 t, %1; cvt.u32.u64 %0, t; }"
        : "=r"(a) : "l"(p));
    return a;
}
__device__ __forceinline__ void ldx4(uint32_t& r0, uint32_t& r1, uint32_t& r2,
                                     uint32_t& r3, uint32_t addr) {
    asm volatile("ldmatrix.sync.aligned.m8n8.x4.shared.b16 {%0,%1,%2,%3}, [%4];"
                 : "=r"(r0), "=r"(r1), "=r"(r2), "=r"(r3) : "r"(addr));
}
__device__ __forceinline__ void mma16816(float* d, const uint32_t* a,
                                         uint32_t b0, uint32_t b1) {
    asm volatile("mma.sync.aligned.m16n8k16.row.col.f32.f16.f16.f32 "
                 "{%0,%1,%2,%3}, {%4,%5,%6,%7}, {%8,%9}, {%0,%1,%2,%3};"
                 : "+f"(d[0]), "+f"(d[1]), "+f"(d[2]), "+f"(d[3])
                 : "r"(a[0]), "r"(a[1]), "r"(a[2]), "r"(a[3]), "r"(b0), "r"(b1));
}
// cp.async 16B with zero-fill when pred==false (src still a valid address)
__device__ __forceinline__ void cpa16(uint32_t dst, const void* src, bool pred) {
    asm volatile("cp.async.cg.shared.global [%0], [%1], 16, %2;"
                 :: "r"(dst), "l"(src), "r"(pred ? 16u : 0u));
}
#define CP_COMMIT()  asm volatile("cp.async.commit_group;" ::: "memory")
#define CP_WAIT0()   asm volatile("cp.async.wait_group 0;" ::: "memory")
#define CP_WAIT1()   asm volatile("cp.async.wait_group 1;" ::: "memory")

// ---------------------------------------------------------------------------
// Prep kernel: blocks [0,1024) transpose x -> pixel-major fp16;
// blocks [1024, ...) convert both weight tensors to (s,O,I) fp16.
// ---------------------------------------------------------------------------
#define WA_ELEMS (9 * 128 * CIN)   // 73728
#define WB_ELEMS (9 *  64 * CIN)   // 36864
#define PREP_WBLOCKS ((WA_ELEMS + WB_ELEMS + 255) / 256)   // 432

__global__ void __launch_bounds__(256)
prep_kernel(const float* __restrict__ x, __half* __restrict__ hi,
            const float* __restrict__ wA, __half* __restrict__ waO,
            const float* __restrict__ wB, __half* __restrict__ wbO)
{
    const int tid = threadIdx.x;
    if (blockIdx.x < 1024) {
        __shared__ float s[CIN][Wd + 1];
        const int y = blockIdx.x & (Hd - 1);
        const int b = blockIdx.x >> 7;
        for (int idx = tid; idx < CIN * Wd; idx += 256) {
            const int c = idx >> 7, xx = idx & (Wd - 1);
            s[c][xx] = x[(((size_t)b * CIN + c) * Hd + y) * Wd + xx];
        }
        __syncthreads();
        for (int idx = tid; idx < Wd * (CIN / 2); idx += 256) {
            const int xx = idx >> 5, cp = idx & 31;
            const __half h0 = __float2half_rn(s[2 * cp][xx]);
            const __half h1 = __float2half_rn(s[2 * cp + 1][xx]);
            const size_t base = ((size_t)(b * Hd + y) * Wd + xx) * CIN + 2 * cp;
            *reinterpret_cast<__half2*>(hi + base) = __halves2half2(h0, h1);
        }
    } else {
        const int g = (blockIdx.x - 1024) * 256 + tid;
        if (g < WA_ELEMS) {
            const int i = g & (CIN - 1);
            const int o = (g >> 6) & 127;
            const int s = g / (CIN * 128);
            waO[g] = __float2half_rn(wA[((size_t)o * CIN + i) * 9 + s]);
        } else if (g < WA_ELEMS + WB_ELEMS) {
            const int g2 = g - WA_ELEMS;
            const int i = g2 & (CIN - 1);
            const int o = (g2 >> 6) & 63;
            const int s = g2 / (CIN * 64);
            wbO[g2] = __float2half_rn(wB[((size_t)o * CIN + i) * 9 + s]);
        }
    }
}

// ---------------------------------------------------------------------------
// conv A: implicit-GEMM 3x3 via mma.sync, dy-outer, split-prologue.
// CTA = one (b, y) row: M=128, N=128, fp16 output.
// ---------------------------------------------------------------------------
template <int COUT, int WARPS_M, int WARPS_N, int MINB, typename OUTT>
__global__ void __launch_bounds__(256, MINB)
conv_mma_kernel(const __half* __restrict__ a_src,
                const __half* __restrict__ w_src,
                const float* __restrict__ bias, OUTT* __restrict__ out)
{
    constexpr int WM = 128 / WARPS_M;
    constexpr int WN = COUT / WARPS_N;
    constexpr int MF = WM / 16;
    constexpr int NF = WN / 8;
    constexpr int LDA = 72;
    constexpr int LDB = 72;
    constexpr int ASEG = 130 * LDA;
    constexpr int BSEG = COUT * LDB;
    constexpr int BOFF = 2 * ASEG;

    extern __shared__ __align__(16) __half smem[];
    const uint32_t sb = smem_u32(smem);

    const int tid  = threadIdx.x;
    const int lane = tid & 31, wid = tid >> 5;
    const int wm = wid % WARPS_M, wn = wid / WARPS_M;
    const int m0 = wm * WM, n0 = wn * WN;
    const int y = blockIdx.x & (Hd - 1);
    const int b = blockIdx.x >> 7;

    auto stageA = [&](int buf, int dy) {
        const int yy = y + dy - 1;
        const bool rowok = (unsigned)yy < (unsigned)Hd;
        const uint32_t dh = sb + (uint32_t)(buf * ASEG) * 2;
        for (int idx = tid; idx < 130 * 8; idx += 256) {
            const int p = idx >> 3, j = idx & 7;
            const int xx = p - 1;
            const bool ok = rowok && (unsigned)xx < (unsigned)Wd;
            const size_t base = ok ? (((size_t)((b * Hd + yy) * Wd + xx)) * CIN + j * 8) : 0;
            const uint32_t doff = (uint32_t)(p * LDA + j * 8) * 2;
            cpa16(dh + doff, a_src + base, ok);
        }
    };
    auto stageB3 = [&](int dy) {
        const int s0 = dy * 3;
        const uint32_t dh = sb + (uint32_t)BOFF * 2;
        for (int idx = tid; idx < 3 * COUT * 8; idx += 256) {
            const int op = idx >> 3, j = idx & 7;
            const size_t base = ((size_t)(s0 * COUT) + op) * CIN + j * 8;
            const uint32_t doff = (uint32_t)(op * LDB + j * 8) * 2;
            cpa16(dh + doff, w_src + base, true);
        }
    };

    float d[MF][NF][4];
#pragma unroll
    for (int i = 0; i < MF; i++)
#pragma unroll
        for (int j = 0; j < NF; j++)
#pragma unroll
            for (int k = 0; k < 4; k++) d[i][j][k] = 0.0f;

    const int a_row = lane & 15;
    const int a_k   = (lane >> 4) << 3;
    const int b_row = ((lane >> 4) << 3) + (lane & 7);
    const int b_k   = ((lane >> 3) & 1) << 3;

    // split prologue: dy0's data in group 1, A(dy1) in group 2
    stageA(0, 0); stageB3(0); CP_COMMIT();
    stageA(1, 1); CP_COMMIT();

#pragma unroll 1
    for (int dy = 0; dy < 3; dy++) {
        if (dy == 0) { CP_WAIT1(); } else { CP_WAIT0(); }
        __syncthreads();
        const uint32_t uAh = sb + (uint32_t)((dy & 1) * ASEG) * 2;

#pragma unroll 1
        for (int dx = 0; dx < 3; dx++) {
            const uint32_t uB = sb + (uint32_t)(BOFF + dx * BSEG) * 2;
#pragma unroll
            for (int kk = 0; kk < 4; kk++) {
                uint32_t ah[MF][4];
#pragma unroll
                for (int mf = 0; mf < MF; mf++) {
                    const uint32_t off =
                        (uint32_t)((m0 + mf * 16 + a_row + dx) * LDA + kk * 16 + a_k) * 2;
                    ldx4(ah[mf][0], ah[mf][1], ah[mf][2], ah[mf][3], uAh + off);
                }
#pragma unroll
                for (int nfp = 0; nfp < NF / 2; nfp++) {
                    const uint32_t boff =
                        (uint32_t)((n0 + nfp * 16 + b_row) * LDB + kk * 16 + b_k) * 2;
                    uint32_t h0, h1, h2, h3;
                    ldx4(h0, h1, h2, h3, uB + boff);
#pragma unroll
                    for (int mf = 0; mf < MF; mf++) {
                        mma16816(d[mf][2 * nfp],     ah[mf], h0, h1);
                        mma16816(d[mf][2 * nfp + 1], ah[mf], h2, h3);
                    }
                }
            }
        }
        __syncthreads();

        if (dy < 2) {
            if (dy == 0) stageA(0, 2);
            stageB3(dy + 1);
        }
        CP_COMMIT();
    }

    // ---- epilogue ----
    float* sEp = reinterpret_cast<float*>(smem);   // COUT x 132
#pragma unroll
    for (int mf = 0; mf < MF; mf++) {
#pragma unroll
        for (int nf = 0; nf < NF; nf++) {
            const int xl = m0 + mf * 16 + (lane >> 2);
            const int c  = n0 + nf * 8 + (lane & 3) * 2;
            sEp[ c      * 132 + xl    ] = d[mf][nf][0];
            sEp[(c + 1) * 132 + xl    ] = d[mf][nf][1];
            sEp[ c      * 132 + xl + 8] = d[mf][nf][2];
            sEp[(c + 1) * 132 + xl + 8] = d[mf][nf][3];
        }
    }
    __syncthreads();
    if (sizeof(OUTT) == 2) {
        for (int idx = tid; idx < COUT * 64; idx += 256) {
            const int c = idx >> 6, qp = idx & 63;
            float v0 = sEp[c * 132 + 2 * qp];
            float v1 = sEp[c * 132 + 2 * qp + 1];
            if (bias) { const float bv = __ldg(bias + c); v0 += bv; v1 += bv; }
            __half2* o2 = reinterpret_cast<__half2*>(
                (__half*)out + (((size_t)b * COUT + c) * Hd + y) * Wd + 2 * qp);
            *o2 = __floats2half2_rn(v0, v1);
        }
    } else {
        for (int idx = tid; idx < COUT * 128; idx += 256) {
            const int c = idx >> 7, q = idx & 127;
            float v = sEp[c * 132 + q];
            if (bias) v += __ldg(bias + c);
            ((float*)out)[(((size_t)b * COUT + c) * Hd + y) * Wd + q] = v;
        }
    }
}

// ---------------------------------------------------------------------------
// conv B: M=256 (two y-rows per CTA), N=64, 4-slot input-row RING.
// Only 4 distinct input rows (y0-1 .. y0+2) exist; stage each exactly once.
// Slot s holds input row y0-1+s (130 halo pixels). dy uses slots dy, dy+1.
// grid = 512. fp32 output + bias.
// ---------------------------------------------------------------------------
__global__ void __launch_bounds__(256, 2)
conv_mma2_kernel(const __half* __restrict__ a_src,
                 const __half* __restrict__ w_src,
                 const float* __restrict__ bias, float* __restrict__ out)
{
    constexpr int COUT = 64;
    constexpr int MF = 4, NF = 4;
    constexpr int LDA = 72, LDB = 72;
    constexpr int ASEG = 130 * LDA;          // one row-slot
    constexpr int BSEG = COUT * LDB;
    constexpr int BOFF = 4 * ASEG;           // 4 slots then B region

    extern __shared__ __align__(16) __half smem[];
    const uint32_t sb = smem_u32(smem);

    const int tid  = threadIdx.x;
    const int lane = tid & 31, wid = tid >> 5;
    const int wm = wid & 3, wn = wid >> 2;       // 4 x 2 warps
    const int m0 = wm * 64, n0 = wn * 32;
    const int y0 = (blockIdx.x & 63) * 2;
    const int b  = blockIdx.x >> 6;

    // stage one input row (y0-1+slot) into slot
    auto stageAslot = [&](int slot) {
        const int yy = y0 - 1 + slot;
        const bool rowok = (unsigned)yy < (unsigned)Hd;
        const uint32_t dh = sb + (uint32_t)(slot * ASEG) * 2;
        for (int idx = tid; idx < 130 * 8; idx += 256) {
            const int p = idx >> 3, j = idx & 7;
            const int xx = p - 1;
            const bool ok = rowok && (unsigned)xx < (unsigned)Wd;
            const size_t base = ok ? (((size_t)((b * Hd + yy) * Wd + xx)) * CIN + j * 8) : 0;
            const uint32_t doff = (uint32_t)(p * LDA + j * 8) * 2;
            cpa16(dh + doff, a_src + base, ok);
        }
    };
    auto stageB3 = [&](int dy) {
        const int s0 = dy * 3;
        const uint32_t dh = sb + (uint32_t)BOFF * 2;
        for (int idx = tid; idx < 3 * COUT * 8; idx += 256) {
            const int op = idx >> 3, j = idx & 7;
            const size_t base = ((size_t)(s0 * COUT) + op) * CIN + j * 8;
            const uint32_t doff = (uint32_t)(op * LDB + j * 8) * 2;
            cpa16(dh + doff, w_src + base, true);
        }
    };

    float d[MF][NF][4];
#pragma unroll
    for (int i = 0; i < MF; i++)
#pragma unroll
        for (int j = 0; j < NF; j++)
#pragma unroll
            for (int k = 0; k < 4; k++) d[i][j][k] = 0.0f;

    const int a_row = lane & 15;
    const int a_k   = (lane >> 4) << 3;
    const int b_row = ((lane >> 4) << 3) + (lane & 7);
    const int b_k   = ((lane >> 3) & 1) << 3;
    const int mloc  = m0 & 127;                  // pixel offset within slot
    const int sext  = (wm >= 2) ? 1 : 0;         // second output row -> slot dy+1

    // prologue: dy0 data (slots 0,1 + B0) in group 1; slots 2,3 in group 2
    stageAslot(0); stageAslot(1); stageB3(0); CP_COMMIT();
    stageAslot(2); stageAslot(3); CP_COMMIT();

#pragma unroll 1
    for (int dy = 0; dy < 3; dy++) {
        if (dy == 0) { CP_WAIT1(); } else { CP_WAIT0(); }
        __syncthreads();

        const uint32_t uA = sb + (uint32_t)((dy + sext) * ASEG) * 2;

#pragma unroll 1
        for (int dx = 0; dx < 3; dx++) {
            const uint32_t uB = sb + (uint32_t)(BOFF + dx * BSEG) * 2;
#pragma unroll
            for (int kk = 0; kk < 4; kk++) {
                uint32_t ah[MF][4];
#pragma unroll
                for (int mf = 0; mf < MF; mf++) {
                    const uint32_t off =
                        (uint32_t)((mloc + mf * 16 + a_row + dx) * LDA + kk * 16 + a_k) * 2;
                    ldx4(ah[mf][0], ah[mf][1], ah[mf][2], ah[mf][3], uA + off);
                }
#pragma unroll
                for (int nfp = 0; nfp < NF / 2; nfp++) {
                    const uint32_t boff =
                        (uint32_t)((n0 + nfp * 16 + b_row) * LDB + kk * 16 + b_k) * 2;
                    uint32_t h0, h1, h2, h3;
                    ldx4(h0, h1, h2, h3, uB + boff);
#pragma unroll
                    for (int mf = 0; mf < MF; mf++) {
                        mma16816(d[mf][2 * nfp],     ah[mf], h0, h1);
                        mma16816(d[mf][2 * nfp + 1], ah[mf], h2, h3);
                    }
                }
            }
        }
        __syncthreads();   // B slots free to restage

        if (dy < 2) stageB3(dy + 1);
        CP_COMMIT();
    }

    // ---- epilogue: COUT x 260 fp32 through smem ----
    float* sEp = reinterpret_cast<float*>(smem);
#pragma unroll
    for (int mf = 0; mf < MF; mf++) {
#pragma unroll
        for (int nf = 0; nf < NF; nf++) {
            const int xl = m0 + mf * 16 + (lane >> 2);
            const int c  = n0 + nf * 8 + (lane & 3) * 2;
            sEp[ c      * 260 + xl    ] = d[mf][nf][0];
            sEp[(c + 1) * 260 + xl    ] = d[mf][nf][1];
            sEp[ c      * 260 + xl + 8] = d[mf][nf][2];
            sEp[(c + 1) * 260 + xl + 8] = d[mf][nf][3];
        }
    }
    __syncthreads();
    for (int idx = tid; idx < COUT * 256; idx += 256) {
        const int c = idx >> 8, q = idx & 255;
        float v = sEp[c * 260 + q] + __ldg(bias + c);
        out[(((size_t)b * COUT + c) * Hd + y0 + (q >> 7)) * Wd + (q & 127)] = v;
    }
}

// ---------------------------------------------------------------------------
// Plane-local deformable gather -> pixel-major fp16, 4-channel ILP.
// ---------------------------------------------------------------------------
__global__ void __launch_bounds__(256)
gather_kernel(const float* __restrict__ x,        // (B, C, H, W)
              const __half* __restrict__ off,     // (B, 2C, H, W) fp16
              __half* __restrict__ xd_hi)
{
    constexpr int LDC = 68;
    extern __shared__ __align__(16) __half gsm[]; // s_hi[256][68]
    __half* s_hi = gsm;

    const int t  = threadIdx.x;
    const int p0 = blockIdx.x * 256;
    const int b  = blockIdx.y;
    const int p  = p0 + t;

    const float gy = (float)(p >> 7);
    const float gx = (float)(p & 127);
    const int   t2 = 2 * p;
    const int   chb = t2 >> 14;
    const int   pos = t2 & (HWd - 1);
    const __half* offb = off + (size_t)b * (2 * CIN) * HWd + pos;
    const float* xb   = x + (size_t)b * CIN * HWd;

#pragma unroll 1
    for (int c = 0; c < CIN; c += 4) {
        // 4 independent channel chains for gather-load MLP
        float2 o[4];
#pragma unroll
        for (int u = 0; u < 4; u++)
            o[u] = __half22float2(*reinterpret_cast<const __half2*>(
                offb + (size_t)(2 * (c + u) + chb) * HWd));

        float cy[4], cx[4], y0f[4], x0f[4];
        int ia[4], ib[4], ic[4], id[4];
#pragma unroll
        for (int u = 0; u < 4; u++) {
            cy[u] = fminf(fmaxf(o[u].x + gy, 0.0f), (float)(Hd - 1));
            cx[u] = fminf(fmaxf(o[u].y + gx, 0.0f), (float)(Wd - 1));
            y0f[u] = floorf(cy[u]);
            x0f[u] = floorf(cx[u]);
            const int yi0 = (int)y0f[u], yi1 = (int)ceilf(cy[u]);
            const int xi0 = (int)x0f[u], xi1 = (int)ceilf(cx[u]);
            ia[u] = yi0 * Wd + xi0;
            ib[u] = yi1 * Wd + xi1;
            ic[u] = yi0 * Wd + xi1;
            id[u] = yi1 * Wd + xi0;
        }
        float v_lt[4], v_rb[4], v_lb[4], v_rt[4];
#pragma unroll
        for (int u = 0; u < 4; u++) {
            const float* xp = xb + (size_t)(c + u) * HWd;
            v_lt[u] = __ldg(xp + ia[u]);
            v_rb[u] = __ldg(xp + ib[u]);
            v_lb[u] = __ldg(xp + ic[u]);
            v_rt[u] = __ldg(xp + id[u]);
        }
#pragma unroll
        for (int u = 0; u < 4; u++) {
            const float dyf = cy[u] - y0f[u];
            const float dxf = cx[u] - x0f[u];
            const float vt = dyf * (v_rt[u] - v_lt[u]) + v_lt[u];
            const float vb = dyf * (v_rb[u] - v_lb[u]) + v_lb[u];
            s_hi[t * LDC + c + u] = __float2half_rn(dxf * (vb - vt) + vt);
        }
    }
    __syncthreads();

    for (int idx = t; idx < 256 * 16; idx += 256) {
        const int pp = idx >> 4, j = idx & 15;
        const uint2 vh = *reinterpret_cast<const uint2*>(s_hi + pp * LDC + j * 4);
        const size_t o = ((size_t)b * HWd + p0 + pp) * CIN + j * 4;
        *reinterpret_cast<uint2*>(xd_hi + o) = vh;
    }
}

// ---------------------------------------------------------------------------
extern "C" void kernel_launch(void* const* d_in, const int* in_sizes, int n_in,
                              void* d_out, int out_size)
{
    const float* x      = (const float*)d_in[0];
    const float* W_off  = (const float*)d_in[1];
    const float* W_conv = (const float*)d_in[2];
    const float* b_conv = (const float*)d_in[3];
    float* out = (float*)d_out;

    __half *off_p, *xt_hi, *xd_hi, *wa_hi, *wb_hi;
    cudaGetSymbolAddress((void**)&off_p, g_off16);
    cudaGetSymbolAddress((void**)&xt_hi, g_xt_hi);
    cudaGetSymbolAddress((void**)&xd_hi, g_xd_hi);
    cudaGetSymbolAddress((void**)&wa_hi, g_wa_hi);
    cudaGetSymbolAddress((void**)&wb_hi, g_wb_hi);

    const int SMEM_A  = (2 * 130 * 72 + 3 * 128 * 72) * 2;   // 92736
    const int SMEM_B2 = (4 * 130 * 72 + 3 *  64 * 72) * 2;   // 102528
    const int SMEM_G  = 256 * 68 * 2;                        // 34816
    cudaFuncSetAttribute((conv_mma_kernel<128, 2, 4, 2, __half>),
                         cudaFuncAttributeMaxDynamicSharedMemorySize, SMEM_A);
    cudaFuncSetAttribute(conv_mma2_kernel,
                         cudaFuncAttributeMaxDynamicSharedMemorySize, SMEM_B2);
    cudaFuncSetAttribute(gather_kernel,
                         cudaFuncAttributeMaxDynamicSharedMemorySize, SMEM_G);

    // 0) prep: transpose + both weight converts in one launch
    prep_kernel<<<1024 + PREP_WBLOCKS, 256>>>(x, xt_hi, W_off, wa_hi, W_conv, wb_hi);

    // 1) offset conv (64 -> 128), fp16, dy-outer, split prologue, fp16 output
    conv_mma_kernel<128, 2, 4, 2, __half><<<Bn * Hd, 256, SMEM_A>>>(
        xt_hi, wa_hi, nullptr, off_p);

    // 2) plane-local deformable gather (fp16 offsets, ILP=4) -> fp16 pixel-major
    gather_kernel<<<dim3(HWd / 256, Bn), 256, SMEM_G>>>(x, off_p, xd_hi);

    // 3) main conv (64 -> 64) + bias, M=256 tiles, 4-slot A ring, fp32 output
    conv_mma2_kernel<<<512, 256, SMEM_B2>>>(xd_hi, wb_hi, b_conv, out);
}

// round 17
// speedup vs baseline: 1.7103x; 1.0520x over previous
#include <cuda_runtime.h>
#include <cuda_fp16.h>
#include <cstdint>

#define Hd   128
#define Wd   128
#define CIN  64
#define HWd  (Hd * Wd)
#define Bn   8

// ---------------- scratch (device globals; allocation is forbidden) --------
__device__ __align__(16) __half g_off16[Bn * 2 * CIN * HWd];   // offsets (B,2C,H,W) fp16
__device__ __align__(16) __half g_xt_hi[Bn * HWd * CIN];       // x pixel-major fp16
__device__ __align__(16) __half g_xd_hi[Bn * HWd * CIN];       // xdef pixel-major fp16
__device__ __align__(16) __half g_wa_hi[9 * 128 * CIN];        // W_off  (s,O,I) fp16
__device__ __align__(16) __half g_wb_hi[9 *  64 * CIN];        // W_conv (s,O,I) fp16

// ---------------- helpers ---------------------------------------------------
__device__ __forceinline__ uint32_t smem_u32(const void* p) {
    uint32_t a;
    asm("{ .reg .u64 t; cvta.to.shared.u64 t, %1; cvt.u32.u64 %0, t; }"
        : "=r"(a) : "l"(p));
    return a;
}
__device__ __forceinline__ void ldx4(uint32_t& r0, uint32_t& r1, uint32_t& r2,
                                     uint32_t& r3, uint32_t addr) {
    asm volatile("ldmatrix.sync.aligned.m8n8.x4.shared.b16 {%0,%1,%2,%3}, [%4];"
                 : "=r"(r0), "=r"(r1), "=r"(r2), "=r"(r3) : "r"(addr));
}
__device__ __forceinline__ void mma16816(float* d, const uint32_t* a,
                                         uint32_t b0, uint32_t b1) {
    asm volatile("mma.sync.aligned.m16n8k16.row.col.f32.f16.f16.f32 "
                 "{%0,%1,%2,%3}, {%4,%5,%6,%7}, {%8,%9}, {%0,%1,%2,%3};"
                 : "+f"(d[0]), "+f"(d[1]), "+f"(d[2]), "+f"(d[3])
                 : "r"(a[0]), "r"(a[1]), "r"(a[2]), "r"(a[3]), "r"(b0), "r"(b1));
}
// cp.async 16B with zero-fill when pred==false (src still a valid address)
__device__ __forceinline__ void cpa16(uint32_t dst, const void* src, bool pred) {
    asm volatile("cp.async.cg.shared.global [%0], [%1], 16, %2;"
                 :: "r"(dst), "l"(src), "r"(pred ? 16u : 0u));
}
#define CP_COMMIT()  asm volatile("cp.async.commit_group;" ::: "memory")
#define CP_WAIT0()   asm volatile("cp.async.wait_group 0;" ::: "memory")
#define CP_WAIT1()   asm volatile("cp.async.wait_group 1;" ::: "memory")

// ---------------------------------------------------------------------------
// Prep kernel: blocks [0,1024) transpose x -> pixel-major fp16;
// blocks [1024, ...) convert both weight tensors to (s,O,I) fp16.
// ---------------------------------------------------------------------------
#define WA_ELEMS (9 * 128 * CIN)   // 73728
#define WB_ELEMS (9 *  64 * CIN)   // 36864
#define PREP_WBLOCKS ((WA_ELEMS + WB_ELEMS + 255) / 256)   // 432

__global__ void __launch_bounds__(256)
prep_kernel(const float* __restrict__ x, __half* __restrict__ hi,
            const float* __restrict__ wA, __half* __restrict__ waO,
            const float* __restrict__ wB, __half* __restrict__ wbO)
{
    const int tid = threadIdx.x;
    if (blockIdx.x < 1024) {
        __shared__ float s[CIN][Wd + 1];
        const int y = blockIdx.x & (Hd - 1);
        const int b = blockIdx.x >> 7;
        for (int idx = tid; idx < CIN * Wd; idx += 256) {
            const int c = idx >> 7, xx = idx & (Wd - 1);
            s[c][xx] = x[(((size_t)b * CIN + c) * Hd + y) * Wd + xx];
        }
        __syncthreads();
        for (int idx = tid; idx < Wd * (CIN / 2); idx += 256) {
            const int xx = idx >> 5, cp = idx & 31;
            const __half h0 = __float2half_rn(s[2 * cp][xx]);
            const __half h1 = __float2half_rn(s[2 * cp + 1][xx]);
            const size_t base = ((size_t)(b * Hd + y) * Wd + xx) * CIN + 2 * cp;
            *reinterpret_cast<__half2*>(hi + base) = __halves2half2(h0, h1);
        }
    } else {
        const int g = (blockIdx.x - 1024) * 256 + tid;
        if (g < WA_ELEMS) {
            const int i = g & (CIN - 1);
            const int o = (g >> 6) & 127;
            const int s = g / (CIN * 128);
            waO[g] = __float2half_rn(wA[((size_t)o * CIN + i) * 9 + s]);
        } else if (g < WA_ELEMS + WB_ELEMS) {
            const int g2 = g - WA_ELEMS;
            const int i = g2 & (CIN - 1);
            const int o = (g2 >> 6) & 63;
            const int s = g2 / (CIN * 64);
            wbO[g2] = __float2half_rn(wB[((size_t)o * CIN + i) * 9 + s]);
        }
    }
}

// ---------------------------------------------------------------------------
// conv A: implicit-GEMM 3x3 via mma.sync, dy-outer, split-prologue.
// CTA = one (b, y) row: M=128, N=128, fp16 output.
// ---------------------------------------------------------------------------
template <int COUT, int WARPS_M, int WARPS_N, int MINB, typename OUTT>
__global__ void __launch_bounds__(256, MINB)
conv_mma_kernel(const __half* __restrict__ a_src,
                const __half* __restrict__ w_src,
                const float* __restrict__ bias, OUTT* __restrict__ out)
{
    constexpr int WM = 128 / WARPS_M;
    constexpr int WN = COUT / WARPS_N;
    constexpr int MF = WM / 16;
    constexpr int NF = WN / 8;
    constexpr int LDA = 72;
    constexpr int LDB = 72;
    constexpr int ASEG = 130 * LDA;
    constexpr int BSEG = COUT * LDB;
    constexpr int BOFF = 2 * ASEG;

    extern __shared__ __align__(16) __half smem[];
    const uint32_t sb = smem_u32(smem);

    const int tid  = threadIdx.x;
    const int lane = tid & 31, wid = tid >> 5;
    const int wm = wid % WARPS_M, wn = wid / WARPS_M;
    const int m0 = wm * WM, n0 = wn * WN;
    const int y = blockIdx.x & (Hd - 1);
    const int b = blockIdx.x >> 7;

    auto stageA = [&](int buf, int dy) {
        const int yy = y + dy - 1;
        const bool rowok = (unsigned)yy < (unsigned)Hd;
        const uint32_t dh = sb + (uint32_t)(buf * ASEG) * 2;
        for (int idx = tid; idx < 130 * 8; idx += 256) {
            const int p = idx >> 3, j = idx & 7;
            const int xx = p - 1;
            const bool ok = rowok && (unsigned)xx < (unsigned)Wd;
            const size_t base = ok ? (((size_t)((b * Hd + yy) * Wd + xx)) * CIN + j * 8) : 0;
            const uint32_t doff = (uint32_t)(p * LDA + j * 8) * 2;
            cpa16(dh + doff, a_src + base, ok);
        }
    };
    auto stageB3 = [&](int dy) {
        const int s0 = dy * 3;
        const uint32_t dh = sb + (uint32_t)BOFF * 2;
        for (int idx = tid; idx < 3 * COUT * 8; idx += 256) {
            const int op = idx >> 3, j = idx & 7;
            const size_t base = ((size_t)(s0 * COUT) + op) * CIN + j * 8;
            const uint32_t doff = (uint32_t)(op * LDB + j * 8) * 2;
            cpa16(dh + doff, w_src + base, true);
        }
    };

    float d[MF][NF][4];
#pragma unroll
    for (int i = 0; i < MF; i++)
#pragma unroll
        for (int j = 0; j < NF; j++)
#pragma unroll
            for (int k = 0; k < 4; k++) d[i][j][k] = 0.0f;

    const int a_row = lane & 15;
    const int a_k   = (lane >> 4) << 3;
    const int b_row = ((lane >> 4) << 3) + (lane & 7);
    const int b_k   = ((lane >> 3) & 1) << 3;

    // split prologue: dy0's data in group 1, A(dy1) in group 2
    stageA(0, 0); stageB3(0); CP_COMMIT();
    stageA(1, 1); CP_COMMIT();

#pragma unroll 1
    for (int dy = 0; dy < 3; dy++) {
        if (dy == 0) { CP_WAIT1(); } else { CP_WAIT0(); }
        __syncthreads();
        const uint32_t uAh = sb + (uint32_t)((dy & 1) * ASEG) * 2;

#pragma unroll 1
        for (int dx = 0; dx < 3; dx++) {
            const uint32_t uB = sb + (uint32_t)(BOFF + dx * BSEG) * 2;
#pragma unroll
            for (int kk = 0; kk < 4; kk++) {
                uint32_t ah[MF][4];
#pragma unroll
                for (int mf = 0; mf < MF; mf++) {
                    const uint32_t off =
                        (uint32_t)((m0 + mf * 16 + a_row + dx) * LDA + kk * 16 + a_k) * 2;
                    ldx4(ah[mf][0], ah[mf][1], ah[mf][2], ah[mf][3], uAh + off);
                }
#pragma unroll
                for (int nfp = 0; nfp < NF / 2; nfp++) {
                    const uint32_t boff =
                        (uint32_t)((n0 + nfp * 16 + b_row) * LDB + kk * 16 + b_k) * 2;
                    uint32_t h0, h1, h2, h3;
                    ldx4(h0, h1, h2, h3, uB + boff);
#pragma unroll
                    for (int mf = 0; mf < MF; mf++) {
                        mma16816(d[mf][2 * nfp],     ah[mf], h0, h1);
                        mma16816(d[mf][2 * nfp + 1], ah[mf], h2, h3);
                    }
                }
            }
        }
        __syncthreads();

        if (dy < 2) {
            if (dy == 0) stageA(0, 2);
            stageB3(dy + 1);
        }
        CP_COMMIT();
    }

    // ---- epilogue ----
    float* sEp = reinterpret_cast<float*>(smem);   // COUT x 132
#pragma unroll
    for (int mf = 0; mf < MF; mf++) {
#pragma unroll
        for (int nf = 0; nf < NF; nf++) {
            const int xl = m0 + mf * 16 + (lane >> 2);
            const int c  = n0 + nf * 8 + (lane & 3) * 2;
            sEp[ c      * 132 + xl    ] = d[mf][nf][0];
            sEp[(c + 1) * 132 + xl    ] = d[mf][nf][1];
            sEp[ c      * 132 + xl + 8] = d[mf][nf][2];
            sEp[(c + 1) * 132 + xl + 8] = d[mf][nf][3];
        }
    }
    __syncthreads();
    if (sizeof(OUTT) == 2) {
        for (int idx = tid; idx < COUT * 64; idx += 256) {
            const int c = idx >> 6, qp = idx & 63;
            float v0 = sEp[c * 132 + 2 * qp];
            float v1 = sEp[c * 132 + 2 * qp + 1];
            if (bias) { const float bv = __ldg(bias + c); v0 += bv; v1 += bv; }
            __half2* o2 = reinterpret_cast<__half2*>(
                (__half*)out + (((size_t)b * COUT + c) * Hd + y) * Wd + 2 * qp);
            *o2 = __floats2half2_rn(v0, v1);
        }
    } else {
        for (int idx = tid; idx < COUT * 128; idx += 256) {
            const int c = idx >> 7, q = idx & 127;
            float v = sEp[c * 132 + q];
            if (bias) v += __ldg(bias + c);
            ((float*)out)[(((size_t)b * COUT + c) * Hd + y) * Wd + q] = v;
        }
    }
}

// ---------------------------------------------------------------------------
// conv B: M=256 (two y-rows per CTA), N=64, 4-slot input-row RING.
// grid = 512. fp32 output + bias.
// ---------------------------------------------------------------------------
__global__ void __launch_bounds__(256, 2)
conv_mma2_kernel(const __half* __restrict__ a_src,
                 const __half* __restrict__ w_src,
                 const float* __restrict__ bias, float* __restrict__ out)
{
    constexpr int COUT = 64;
    constexpr int MF = 4, NF = 4;
    constexpr int LDA = 72, LDB = 72;
    constexpr int ASEG = 130 * LDA;          // one row-slot
    constexpr int BSEG = COUT * LDB;
    constexpr int BOFF = 4 * ASEG;           // 4 slots then B region

    extern __shared__ __align__(16) __half smem[];
    const uint32_t sb = smem_u32(smem);

    const int tid  = threadIdx.x;
    const int lane = tid & 31, wid = tid >> 5;
    const int wm = wid & 3, wn = wid >> 2;       // 4 x 2 warps
    const int m0 = wm * 64, n0 = wn * 32;
    const int y0 = (blockIdx.x & 63) * 2;
    const int b  = blockIdx.x >> 6;

    auto stageAslot = [&](int slot) {
        const int yy = y0 - 1 + slot;
        const bool rowok = (unsigned)yy < (unsigned)Hd;
        const uint32_t dh = sb + (uint32_t)(slot * ASEG) * 2;
        for (int idx = tid; idx < 130 * 8; idx += 256) {
            const int p = idx >> 3, j = idx & 7;
            const int xx = p - 1;
            const bool ok = rowok && (unsigned)xx < (unsigned)Wd;
            const size_t base = ok ? (((size_t)((b * Hd + yy) * Wd + xx)) * CIN + j * 8) : 0;
            const uint32_t doff = (uint32_t)(p * LDA + j * 8) * 2;
            cpa16(dh + doff, a_src + base, ok);
        }
    };
    auto stageB3 = [&](int dy) {
        const int s0 = dy * 3;
        const uint32_t dh = sb + (uint32_t)BOFF * 2;
        for (int idx = tid; idx < 3 * COUT * 8; idx += 256) {
            const int op = idx >> 3, j = idx & 7;
            const size_t base = ((size_t)(s0 * COUT) + op) * CIN + j * 8;
            const uint32_t doff = (uint32_t)(op * LDB + j * 8) * 2;
            cpa16(dh + doff, w_src + base, true);
        }
    };

    float d[MF][NF][4];
#pragma unroll
    for (int i = 0; i < MF; i++)
#pragma unroll
        for (int j = 0; j < NF; j++)
#pragma unroll
            for (int k = 0; k < 4; k++) d[i][j][k] = 0.0f;

    const int a_row = lane & 15;
    const int a_k   = (lane >> 4) << 3;
    const int b_row = ((lane >> 4) << 3) + (lane & 7);
    const int b_k   = ((lane >> 3) & 1) << 3;
    const int mloc  = m0 & 127;                  // pixel offset within slot
    const int sext  = (wm >= 2) ? 1 : 0;         // second output row -> slot dy+1

    // prologue: dy0 data (slots 0,1 + B0) in group 1; slots 2,3 in group 2
    stageAslot(0); stageAslot(1); stageB3(0); CP_COMMIT();
    stageAslot(2); stageAslot(3); CP_COMMIT();

#pragma unroll 1
    for (int dy = 0; dy < 3; dy++) {
        if (dy == 0) { CP_WAIT1(); } else { CP_WAIT0(); }
        __syncthreads();

        const uint32_t uA = sb + (uint32_t)((dy + sext) * ASEG) * 2;

#pragma unroll 1
        for (int dx = 0; dx < 3; dx++) {
            const uint32_t uB = sb + (uint32_t)(BOFF + dx * BSEG) * 2;
#pragma unroll
            for (int kk = 0; kk < 4; kk++) {
                uint32_t ah[MF][4];
#pragma unroll
                for (int mf = 0; mf < MF; mf++) {
                    const uint32_t off =
                        (uint32_t)((mloc + mf * 16 + a_row + dx) * LDA + kk * 16 + a_k) * 2;
                    ldx4(ah[mf][0], ah[mf][1], ah[mf][2], ah[mf][3], uA + off);
                }
#pragma unroll
                for (int nfp = 0; nfp < NF / 2; nfp++) {
                    const uint32_t boff =
                        (uint32_t)((n0 + nfp * 16 + b_row) * LDB + kk * 16 + b_k) * 2;
                    uint32_t h0, h1, h2, h3;
                    ldx4(h0, h1, h2, h3, uB + boff);
#pragma unroll
                    for (int mf = 0; mf < MF; mf++) {
                        mma16816(d[mf][2 * nfp],     ah[mf], h0, h1);
                        mma16816(d[mf][2 * nfp + 1], ah[mf], h2, h3);
                    }
                }
            }
        }
        __syncthreads();   // B slots free to restage

        if (dy < 2) stageB3(dy + 1);
        CP_COMMIT();
    }

    // ---- epilogue: COUT x 260 fp32 through smem ----
    float* sEp = reinterpret_cast<float*>(smem);
#pragma unroll
    for (int mf = 0; mf < MF; mf++) {
#pragma unroll
        for (int nf = 0; nf < NF; nf++) {
            const int xl = m0 + mf * 16 + (lane >> 2);
            const int c  = n0 + nf * 8 + (lane & 3) * 2;
            sEp[ c      * 260 + xl    ] = d[mf][nf][0];
            sEp[(c + 1) * 260 + xl    ] = d[mf][nf][1];
            sEp[ c      * 260 + xl + 8] = d[mf][nf][2];
            sEp[(c + 1) * 260 + xl + 8] = d[mf][nf][3];
        }
    }
    __syncthreads();
    for (int idx = tid; idx < COUT * 256; idx += 256) {
        const int c = idx >> 8, q = idx & 255;
        float v = sEp[c * 260 + q] + __ldg(bias + c);
        out[(((size_t)b * COUT + c) * Hd + y0 + (q >> 7)) * Wd + (q & 127)] = v;
    }
}

// ---------------------------------------------------------------------------
// Deformable gather -> pixel-major fp16. Block = 32 pixels x 8 channel-lane
// warps; each warp owns an 8-channel band of ONE plane neighborhood at a time
// (L1-resident corners, coalesced offset loads). Fully unrolled -> high MLP.
// ---------------------------------------------------------------------------
__global__ void __launch_bounds__(256)
gather_kernel(const float* __restrict__ x,        // (B, C, H, W)
              const __half* __restrict__ off,     // (B, 2C, H, W) fp16
              __half* __restrict__ xd_hi)
{
    constexpr int LDC = 70;                       // halves; px*35 mod 32: no conflicts
    __shared__ __half s_hi[32 * LDC];

    const int tid   = threadIdx.x;
    const int clane = tid >> 5;                   // warp id = channel band
    const int pxl   = tid & 31;
    const int p0    = blockIdx.x * 32;
    const int b     = blockIdx.y;
    const int p     = p0 + pxl;

    const float gy = (float)(p >> 7);
    const float gx = (float)(p & 127);
    const int   t2 = 2 * p;
    const int   chb = t2 >> 14;
    const int   pos = t2 & (HWd - 1);
    const __half* offb = off + (size_t)b * (2 * CIN) * HWd + pos;
    const float* xb   = x + (size_t)b * CIN * HWd;

#pragma unroll
    for (int u = 0; u < 8; u++) {
        const int c = clane * 8 + u;
        const float2 o2 = __half22float2(*reinterpret_cast<const __half2*>(
            offb + (size_t)(2 * c + chb) * HWd));

        float cy = fminf(fmaxf(o2.x + gy, 0.0f), (float)(Hd - 1));
        float cx = fminf(fmaxf(o2.y + gx, 0.0f), (float)(Wd - 1));

        const float y0f = floorf(cy), x0f = floorf(cx);
        const int yi0 = (int)y0f, yi1 = (int)ceilf(cy);
        const int xi0 = (int)x0f, xi1 = (int)ceilf(cx);

        const float* xp = xb + (size_t)c * HWd;
        const float v_lt = __ldg(xp + yi0 * Wd + xi0);
        const float v_rb = __ldg(xp + yi1 * Wd + xi1);
        const float v_lb = __ldg(xp + yi0 * Wd + xi1);
        const float v_rt = __ldg(xp + yi1 * Wd + xi0);

        const float dyf = cy - y0f;
        const float dxf = cx - x0f;
        const float vt = dyf * (v_rt - v_lt) + v_lt;
        const float vb = dyf * (v_rb - v_lb) + v_lb;
        s_hi[pxl * LDC + c] = __float2half_rn(dxf * (vb - vt) + vt);
    }
    __syncthreads();

    // write-out: per warp one pixel row of 64 ch = 128B contiguous
    for (int idx = tid; idx < 32 * 32; idx += 256) {
        const int pp = idx >> 5, j = idx & 31;    // j indexes half2 pairs
        const uint32_t v = *reinterpret_cast<const uint32_t*>(s_hi + pp * LDC + j * 2);
        *reinterpret_cast<uint32_t*>(
            xd_hi + ((size_t)b * HWd + p0 + pp) * CIN + j * 2) = v;
    }
}

// ---------------------------------------------------------------------------
extern "C" void kernel_launch(void* const* d_in, const int* in_sizes, int n_in,
                              void* d_out, int out_size)
{
    const float* x      = (const float*)d_in[0];
    const float* W_off  = (const float*)d_in[1];
    const float* W_conv = (const float*)d_in[2];
    const float* b_conv = (const float*)d_in[3];
    float* out = (float*)d_out;

    __half *off_p, *xt_hi, *xd_hi, *wa_hi, *wb_hi;
    cudaGetSymbolAddress((void**)&off_p, g_off16);
    cudaGetSymbolAddress((void**)&xt_hi, g_xt_hi);
    cudaGetSymbolAddress((void**)&xd_hi, g_xd_hi);
    cudaGetSymbolAddress((void**)&wa_hi, g_wa_hi);
    cudaGetSymbolAddress((void**)&wb_hi, g_wb_hi);

    const int SMEM_A  = (2 * 130 * 72 + 3 * 128 * 72) * 2;   // 92736
    const int SMEM_B2 = (4 * 130 * 72 + 3 *  64 * 72) * 2;   // 102528
    cudaFuncSetAttribute((conv_mma_kernel<128, 2, 4, 2, __half>),
                         cudaFuncAttributeMaxDynamicSharedMemorySize, SMEM_A);
    cudaFuncSetAttribute(conv_mma2_kernel,
                         cudaFuncAttributeMaxDynamicSharedMemorySize, SMEM_B2);

    // 0) prep: transpose + both weight converts in one launch
    prep_kernel<<<1024 + PREP_WBLOCKS, 256>>>(x, xt_hi, W_off, wa_hi, W_conv, wb_hi);

    // 1) offset conv (64 -> 128), fp16, dy-outer, split prologue, fp16 output
    conv_mma_kernel<128, 2, 4, 2, __half><<<Bn * Hd, 256, SMEM_A>>>(
        xt_hi, wa_hi, nullptr, off_p);

    // 2) deformable gather (32px x 8ch-warp blocks) -> fp16 pixel-major
    gather_kernel<<<dim3(HWd / 32, Bn), 256>>>(x, off_p, xd_hi);

    // 3) main conv (64 -> 64) + bias, M=256 tiles, 4-slot A ring, fp32 output
    conv_mma2_kernel<<<512, 256, SMEM_B2>>>(xd_hi, wb_hi, b_conv, out);
}